// round 11
// baseline (speedup 1.0000x reference)
#include <cuda_runtime.h>
#include <cuda_fp16.h>
#include <math.h>
#include <stdint.h>

#define SP    512
#define DIN   1536
#define NH    32
#define HD    128
#define HDTOT 4096
#define KS    3072   // 2*DIN  (fp16 2-term split)
#define KHS   256    // 2*HD

// ---------------- scratch ----------------
__device__ __half g_Xn[SP*KS];
__device__ __half g_Xg[SP*KS];
__device__ __half g_Ww[(size_t)2*HDTOT*KS];
__device__ __half g_Wy[2*HD*KS];
__device__ float g_q[SP*HDTOT];
__device__ float g_k[SP*HDTOT];
__device__ float g_yq[SP*HD];
__device__ float g_yk[SP*HD];
__device__ __half g_Qs[(size_t)NH*SP*KHS];
__device__ __half g_Ks[(size_t)NH*SP*KHS];
__device__ float g_S[(size_t)NH*SP*SP];
__device__ float g_TQ[33*SP*NH*2];
__device__ float g_TK[33*SP*NH*2];
__device__ float g_RQ[33*SP*HD*2];
__device__ float g_RK[33*SP*HD*2];
__device__ int   g_f0[SP];

// ---------------- helpers ----------------
__device__ __forceinline__ uint32_t smem_u32(const void* p) {
    uint32_t a;
    asm("{ .reg .u64 t; cvta.to.shared.u64 t, %1; cvt.u32.u64 %0, t; }" : "=r"(a) : "l"(p));
    return a;
}
__device__ __forceinline__ void cp16(uint32_t dst, const void* src) {
    asm volatile("cp.async.cg.shared.global [%0], [%1], 16;" :: "r"(dst), "l"(src));
}
#define CP_COMMIT() asm volatile("cp.async.commit_group;" ::: "memory")
#define CP_WAIT1()  asm volatile("cp.async.wait_group 1;" ::: "memory")

__device__ __forceinline__ void ldm_x4(uint32_t* r, uint32_t addr) {
    asm volatile("ldmatrix.sync.aligned.m8n8.x4.shared.b16 {%0,%1,%2,%3}, [%4];"
                 : "=r"(r[0]), "=r"(r[1]), "=r"(r[2]), "=r"(r[3]) : "r"(addr));
}
__device__ __forceinline__ void mma16816(float* c, const uint32_t* a, uint32_t b0, uint32_t b1) {
    asm volatile("mma.sync.aligned.m16n8k16.row.col.f32.f16.f16.f32 "
                 "{%0,%1,%2,%3}, {%4,%5,%6,%7}, {%8,%9}, {%0,%1,%2,%3};"
                 : "+f"(c[0]), "+f"(c[1]), "+f"(c[2]), "+f"(c[3])
                 : "r"(a[0]), "r"(a[1]), "r"(a[2]), "r"(a[3]), "r"(b0), "r"(b1));
}
__device__ __forceinline__ void split2h(float v, __half& hi, __half& lo) {
    hi = __float2half(v);
    lo = __float2half(v - __half2float(hi));
}

// BK=64: A tile 128x72 fp16 (144 B/row), B tile 256x72 fp16
#define A_TILE 18432
#define B_TILE 36864
#define STAGE_BYTES (A_TILE + B_TILE)
#define MMA_SMEM (3 * STAGE_BYTES)

__device__ __forceinline__ void mma_mainloop(
    uint32_t smb, const __half* __restrict__ Ab,
    const __half* __restrict__ Bb, int sA, int sB, int niter,
    int t, int lane, int wm, int wn, float c[4][8][4])
{
    uint32_t aoff[4], boff[4];
    {
        int lr = lane & 15, lc = lane >> 4;
        #pragma unroll
        for (int mi = 0; mi < 4; mi++) aoff[mi] = (wm * 64 + mi * 16 + lr) * 144 + lc * 16;
        #pragma unroll
        for (int nj = 0; nj < 4; nj++) boff[nj] = A_TILE + (wn * 64 + nj * 16 + lr) * 144 + lc * 16;
    }
    int lrow = t >> 3;
    int lc16 = (t & 7) * 16;
    int lcol_el = (t & 7) * 8;

    #pragma unroll
    for (int s = 0; s < 2; s++) {
        uint32_t db = smb + s * STAGE_BYTES;
        #pragma unroll
        for (int i = 0; i < 4; i++) {
            int row = lrow + i * 32;
            cp16(db + row * 144 + lc16, Ab + (size_t)row * sA + s * 64 + lcol_el);
        }
        #pragma unroll
        for (int i = 0; i < 8; i++) {
            int row = lrow + i * 32;
            cp16(db + A_TILE + row * 144 + lc16, Bb + (size_t)row * sB + s * 64 + lcol_el);
        }
        CP_COMMIT();
    }

    for (int ck = 0; ck < niter; ck++) {
        CP_WAIT1();
        __syncthreads();
        int pf = ck + 2;
        if (pf < niter) {
            uint32_t db = smb + (pf % 3) * STAGE_BYTES;
            #pragma unroll
            for (int i = 0; i < 4; i++) {
                int row = lrow + i * 32;
                cp16(db + row * 144 + lc16, Ab + (size_t)row * sA + pf * 64 + lcol_el);
            }
            #pragma unroll
            for (int i = 0; i < 8; i++) {
                int row = lrow + i * 32;
                cp16(db + A_TILE + row * 144 + lc16, Bb + (size_t)row * sB + pf * 64 + lcol_el);
            }
        }
        CP_COMMIT();
        uint32_t sa = smb + (ck % 3) * STAGE_BYTES;
        #pragma unroll
        for (int kk = 0; kk < 4; kk++) {
            uint32_t a[4][4], b[4][4];
            #pragma unroll
            for (int mi = 0; mi < 4; mi++) ldm_x4(a[mi], sa + aoff[mi] + kk * 32);
            #pragma unroll
            for (int nj = 0; nj < 4; nj++) ldm_x4(b[nj], sa + boff[nj] + kk * 32);
            #pragma unroll
            for (int mi = 0; mi < 4; mi++)
                #pragma unroll
                for (int ni = 0; ni < 8; ni++)
                    mma16816(c[mi][ni], a[mi], b[ni >> 1][ni & 1], b[ni >> 1][(ni & 1) + 2]);
        }
    }
}

// ---------------- K1: pool + rmsnorm + gelu -> fp16 [hi,lo] ----------------
__global__ void k_pool(const float* __restrict__ x, const float* __restrict__ w_rms,
                       __half* __restrict__ Xn, __half* __restrict__ Xg) {
    int sp = blockIdx.x;
    const float* xb = x + (size_t)sp * 16 * DIN;
    __shared__ float xp[DIN];
    __shared__ float red[256];
    int t = threadIdx.x;
    float ssq = 0.f;
    for (int c = t; c < DIN; c += 256) {
        float s = 0.f;
        #pragma unroll
        for (int r = 0; r < 16; r++) s += xb[r * DIN + c];
        s *= (1.f / 16.f);
        xp[c] = s;
        ssq += s * s;
    }
    red[t] = ssq;
    __syncthreads();
    for (int o = 128; o > 0; o >>= 1) {
        if (t < o) red[t] += red[t + o];
        __syncthreads();
    }
    float scale = rsqrtf(red[0] / (float)DIN + 1e-6f);
    size_t b = (size_t)sp * KS;
    for (int c = t; c < DIN; c += 256) {
        float v = xp[c] * scale * w_rms[c];
        __half hi, lo;
        split2h(v, hi, lo);
        Xn[b + c] = hi; Xn[b + DIN + c] = lo;
        float g = v * normcdff(v);
        split2h(g, hi, lo);
        Xg[b + c] = hi; Xg[b + DIN + c] = lo;
    }
}

// ---------------- K2: f0 table ----------------
__global__ void k_f0(int* __restrict__ f0) {
    int d = threadIdx.x;
    if (d < SP) {
        const float log_step = (float)(log(481.0) / 32.0);
        int cnt = 0;
        #pragma unroll
        for (int f = 0; f < 32; f++) {
            float cw = (float)f + expf((float)f * log_step);
            if (cw <= (float)d) cnt++;
        }
        f0[d] = cnt;
    }
}

// ---------------- K4: transpose weights -> fp16 [hi,hi] ----------------
__global__ void k_wsplit(const float* __restrict__ srcA, const float* __restrict__ srcB,
                         int Nsrc, __half* __restrict__ dst) {
    __shared__ float tile[32][33];
    int t = threadIdx.x;
    int n0 = blockIdx.x * 32, k0 = blockIdx.y * 32;
    const float* src = (n0 < Nsrc) ? srcA : srcB;
    int nb = (n0 < Nsrc) ? n0 : (n0 - Nsrc);
    #pragma unroll
    for (int i = 0; i < 4; i++) {
        int r = (t >> 5) + i * 8, c = t & 31;
        tile[r][c] = src[(size_t)(k0 + r) * Nsrc + nb + c];
    }
    __syncthreads();
    #pragma unroll
    for (int i = 0; i < 4; i++) {
        int rn = (t >> 5) + i * 8;
        int kk = k0 + (t & 31);
        __half hi = __float2half(tile[t & 31][rn]);
        size_t row = (size_t)(n0 + rn) * KS;
        dst[row + kk] = hi;
        dst[row + DIN + kk] = hi;
    }
}

// ---------------- K5: fused projection GEMM (CTA 128x256) ----------------
__global__ void __launch_bounds__(256) k_proj(
    const __half* __restrict__ Xn, const __half* __restrict__ Xg,
    const __half* __restrict__ Ww, const __half* __restrict__ Wy,
    float* __restrict__ q, float* __restrict__ k,
    float* __restrict__ yq, float* __restrict__ yk)
{
    extern __shared__ char sm[];
    uint32_t smb = smem_u32(sm);
    int t = threadIdx.x, w = t >> 5, lane = t & 31;
    int wm = w >> 2, wn = w & 3;
    int bid = blockIdx.x;
    int mt, nt;
    if (bid < 128) { mt = bid & 3; nt = bid >> 2; }
    else { mt = bid - 128; nt = 32; }

    const __half* Ab = (bid < 128) ? (Xn + (size_t)mt * 128 * KS)
                                   : (Xg + (size_t)mt * 128 * KS);
    const __half* Bb = (nt < 32) ? (Ww + (size_t)nt * 256 * KS) : Wy;

    float c[4][8][4];
    #pragma unroll
    for (int i = 0; i < 4; i++)
        #pragma unroll
        for (int j = 0; j < 8; j++)
            #pragma unroll
            for (int e = 0; e < 4; e++) c[i][j][e] = 0.f;

    mma_mainloop(smb, Ab, Bb, KS, KS, KS / 64, t, lane, wm, wn, c);

    int r0 = lane >> 2, c0 = (lane & 3) * 2;
    int srow0 = mt * 128;
    #pragma unroll
    for (int mi = 0; mi < 4; mi++) {
        #pragma unroll
        for (int ni = 0; ni < 8; ni++) {
            #pragma unroll
            for (int half = 0; half < 2; half++) {
                int s = srow0 + wm * 64 + mi * 16 + r0 + half * 8;
                int colL = wn * 64 + ni * 8 + c0;
                float2 fv = make_float2(c[mi][ni][half * 2], c[mi][ni][half * 2 + 1]);
                if (nt < 32) {
                    int col = nt * 256 + colL;
                    bool isQ = col < HDTOT;
                    float* o = isQ ? q : k;
                    int nn = isQ ? col : col - HDTOT;
                    *(float2*)&o[(size_t)s * HDTOT + nn] = fv;
                } else {
                    float* o = (colL < HD) ? yq : yk;
                    int nn = (colL < HD) ? colL : colL - HD;
                    *(float2*)&o[(size_t)s * HD + nn] = fv;
                }
            }
        }
    }
}

// ---------------- K5s: scores GEMM (CTA 128x256, batched over heads) ----------------
__global__ void __launch_bounds__(256) k_scores(
    const __half* __restrict__ Qs, const __half* __restrict__ Ks,
    float* __restrict__ S)
{
    extern __shared__ char sm[];
    uint32_t smb = smem_u32(sm);
    int t = threadIdx.x, w = t >> 5, lane = t & 31;
    int wm = w >> 2, wn = w & 3;
    int m0 = blockIdx.x * 128, n0 = blockIdx.y * 256, z = blockIdx.z;

    const __half* Ab = Qs + (size_t)z * SP * KHS + (size_t)m0 * KHS;
    const __half* Bb = Ks + (size_t)z * SP * KHS + (size_t)n0 * KHS;

    float c[4][8][4];
    #pragma unroll
    for (int i = 0; i < 4; i++)
        #pragma unroll
        for (int j = 0; j < 8; j++)
            #pragma unroll
            for (int e = 0; e < 4; e++) c[i][j][e] = 0.f;

    mma_mainloop(smb, Ab, Bb, KHS, KHS, KHS / 64, t, lane, wm, wn, c);

    int r0 = lane >> 2, c0 = (lane & 3) * 2;
    #pragma unroll
    for (int mi = 0; mi < 4; mi++) {
        #pragma unroll
        for (int ni = 0; ni < 8; ni++) {
            #pragma unroll
            for (int half = 0; half < 2; half++) {
                int row = m0 + wm * 64 + mi * 16 + r0 + half * 8;
                int col = n0 + wn * 64 + ni * 8 + c0;
                float2 fv = make_float2(c[mi][ni][half * 2], c[mi][ni][half * 2 + 1]);
                *(float2*)&S[((size_t)(z * SP + row)) * SP + col] = fv;
            }
        }
    }
}

// ---------------- K5b: coalesced split of q/k -> Qs/Ks ----------------
__global__ void k_splitqk(const float* __restrict__ q, const float* __restrict__ k,
                          __half* __restrict__ Qs, __half* __restrict__ Ks) {
    int idx = blockIdx.x * 256 + threadIdx.x;
    int s = idx >> 12, n = idx & 4095;
    int h = n >> 7, c = n & 127;
    size_t base = ((size_t)h * SP + s) * KHS + c;
    __half hi, lo;
    split2h(q[idx], hi, lo);
    Qs[base] = hi; Qs[base + HD] = lo;
    __half khi = __float2half(k[idx]);
    Ks[base] = khi; Ks[base + HD] = khi;
}

// ---------------- K6: suffix tables ----------------
__global__ void __launch_bounds__(256) k_suffix(const float* __restrict__ qk,
                                                const float* __restrict__ rbias,
                                                const float* __restrict__ W_pos,
                                                const float* __restrict__ b_pos,
                                                float* __restrict__ T) {
    extern __shared__ float smf[];
    float* ws = smf;
    float* qs = ws + 65 * 132;
    float* Ms = qs + 32 * 132;
    int h = blockIdx.y;
    int q0 = blockIdx.x * 32;
    int t = threadIdx.x;
    for (int i = t; i < 65 * 128; i += 256) {
        int f = i >> 7, c = i & 127;
        ws[f * 132 + c] = (f < 64) ? W_pos[f * HDTOT + h * HD + c] : b_pos[h * HD + c];
    }
    for (int i = t; i < 32 * 128; i += 256) {
        int r = i >> 7, c = i & 127;
        qs[r * 132 + c] = qk[(size_t)(q0 + r) * HDTOT + h * HD + c] + rbias[h * HD + c];
    }
    __syncthreads();
    for (int i = t; i < 32 * 65; i += 256) {
        int r = i / 65, f = i % 65;
        const float4* qr = (const float4*)&qs[r * 132];
        const float4* wr = (const float4*)&ws[f * 132];
        float acc = 0.f;
        #pragma unroll
        for (int c4 = 0; c4 < 32; c4++) {
            float4 a = qr[c4], b = wr[c4];
            acc += a.x * b.x + a.y * b.y + a.z * b.z + a.w * b.w;
        }
        Ms[r * 65 + f] = acc;
    }
    __syncthreads();
    for (int i = t; i < 32 * 33; i += 256) {
        int r = i / 33, j = i % 33;
        float sa = Ms[r * 65 + 64];
        float sb = 0.f;
        for (int f = j; f < 32; f++) { sa += Ms[r * 65 + f]; sb += Ms[r * 65 + 32 + f]; }
        int q = q0 + r;
        T[((j * SP + q) * NH + h) * 2] = sa;
        T[((j * SP + q) * NH + h) * 2 + 1] = sb;
    }
}

// ---------------- K7: fold suffix tables through W_pair ----------------
__global__ void __launch_bounds__(128) k_fold(const float* __restrict__ TQ,
                                              const float* __restrict__ TK,
                                              const float* __restrict__ Wp,
                                              float* __restrict__ RQ,
                                              float* __restrict__ RK) {
    __shared__ float tq[33 * 64], tk[33 * 64];
    int q = blockIdx.x, t = threadIdx.x;
    for (int i = t; i < 33 * 64; i += 128) {
        int j = i >> 6, r = i & 63;
        tq[i] = TQ[((size_t)j * SP + q) * 64 + r];
        tk[i] = TK[((size_t)j * SP + q) * 64 + r];
    }
    float wcol[NH];
    #pragma unroll
    for (int h = 0; h < NH; h++) wcol[h] = Wp[h * HD + t];
    __syncthreads();
    for (int j = 0; j < 33; j++) {
        float aa = 0.f, ab = 0.f, ba = 0.f, bb = 0.f;
        const float* tqj = &tq[j * 64];
        const float* tkj = &tk[j * 64];
        #pragma unroll
        for (int h = 0; h < NH; h++) {
            float w = wcol[h];
            aa += tqj[2 * h] * w;  ab += tqj[2 * h + 1] * w;
            ba += tkj[2 * h] * w;  bb += tkj[2 * h + 1] * w;
        }
        size_t ob = ((size_t)j * SP + q) * 256 + t * 2;
        RQ[ob] = aa; RQ[ob + 1] = ab;
        RK[ob] = ba; RK[ob + 1] = bb;
    }
}

// ---------------- K8: pair epilogue GEMM (tensor-core h-contraction) ----------------
// Per block: fixed q, 128-wide k tile. A = S[k][96 split], B = Wp[d][96 split].
// out[q,k,d] = (S @ Wp) + bp[d] + yq[q,d] + yk[k,d] + rel(q,k,d)
#define P2_ROW 208                       // 96 halves = 192 B + 16 pad
#define P2_B_OFF (128 * P2_ROW)          // 26624
#define P2_SMEM  (2 * 128 * P2_ROW + 1024)
__global__ void __launch_bounds__(256) k_pair2(const float* __restrict__ S,
                                               const float* __restrict__ RQ,
                                               const float* __restrict__ RK,
                                               const int* __restrict__ f0tab,
                                               const float* __restrict__ Wp,
                                               const float* __restrict__ bp,
                                               const float* __restrict__ yq,
                                               const float* __restrict__ yk,
                                               float* __restrict__ out) {
    extern __shared__ char sm[];
    uint32_t smb = smem_u32(sm);
    __half* Ssm = (__half*)sm;                       // [k 128][P2_ROW bytes]
    __half* Wsm = (__half*)(sm + P2_B_OFF);          // [d 128][P2_ROW bytes]
    float* yqs = (float*)(sm + 2 * P2_B_OFF);        // [128]
    int t = threadIdx.x, w = t >> 5, lane = t & 31;
    int wm = w >> 2, wn = w & 3;
    int q = blockIdx.x, k0 = blockIdx.y * 128;

    // load S planes -> 3-term split [hi,lo,hi] ; Wp -> [hi,hi,lo]
    for (int i = t; i < NH * 128; i += 256) {
        int h = i >> 7, kl = i & 127;
        float s = S[((size_t)(h * SP + q)) * SP + k0 + kl];
        __half hi, lo;
        split2h(s, hi, lo);
        __half* row = (__half*)(sm + kl * P2_ROW);
        row[h] = hi; row[32 + h] = lo; row[64 + h] = hi;

        float wv = Wp[h * HD + kl];   // kl as d here
        split2h(wv, hi, lo);
        __half* wrow = (__half*)(sm + P2_B_OFF + kl * P2_ROW);
        wrow[h] = hi; wrow[32 + h] = hi; wrow[64 + h] = lo;
    }
    if (t < 128) yqs[t] = yq[q * HD + t] + bp[t];
    __syncthreads();

    // mma: 128(k) x 128(d) x 96, warps 2(m) x 4(n), warp 64x32
    uint32_t aoff[4], boff[2];
    {
        int lr = lane & 15, lc = lane >> 4;
        #pragma unroll
        for (int mi = 0; mi < 4; mi++) aoff[mi] = smb + (wm * 64 + mi * 16 + lr) * P2_ROW + lc * 16;
        #pragma unroll
        for (int nj = 0; nj < 2; nj++) boff[nj] = smb + P2_B_OFF + (wn * 32 + nj * 16 + lr) * P2_ROW + lc * 16;
    }
    float c[4][4][4];
    #pragma unroll
    for (int i = 0; i < 4; i++)
        #pragma unroll
        for (int j = 0; j < 4; j++)
            #pragma unroll
            for (int e = 0; e < 4; e++) c[i][j][e] = 0.f;

    #pragma unroll
    for (int kk = 0; kk < 6; kk++) {
        uint32_t a[4][4], b[2][4];
        #pragma unroll
        for (int mi = 0; mi < 4; mi++) ldm_x4(a[mi], aoff[mi] + kk * 32);
        #pragma unroll
        for (int nj = 0; nj < 2; nj++) ldm_x4(b[nj], boff[nj] + kk * 32);
        #pragma unroll
        for (int mi = 0; mi < 4; mi++)
            #pragma unroll
            for (int ni = 0; ni < 4; ni++)
                mma16816(c[mi][ni], a[mi], b[ni >> 1][ni & 1], b[ni >> 1][(ni & 1) + 2]);
    }

    // epilogue with rel gathers
    int r0 = lane >> 2, c0 = (lane & 3) * 2;
    #pragma unroll
    for (int mi = 0; mi < 4; mi++) {
        #pragma unroll
        for (int half = 0; half < 2; half++) {
            int kl = wm * 64 + mi * 16 + r0 + half * 8;
            int k = k0 + kl;
            int delta = k - q;
            int dd = delta >= 0 ? delta : -delta;
            float sgn = delta > 0 ? 1.f : (delta < 0 ? -1.f : 0.f);
            int j = f0tab[dd];
            const float* rqb = &RQ[((size_t)j * SP + q) * 256];
            const float* rkb = &RK[((size_t)j * SP + k) * 256];
            float* ob = &out[((size_t)(q * SP + k)) * HD];
            const float* ykb = &yk[k * HD];
            #pragma unroll
            for (int ni = 0; ni < 4; ni++) {
                int d = wn * 32 + ni * 8 + c0;
                float4 rq = *(const float4*)&rqb[d * 2];
                float4 rk = *(const float4*)&rkb[d * 2];
                float2 ykv = *(const float2*)&ykb[d];
                float o0 = c[mi][ni][half * 2] + yqs[d] + ykv.x
                         + 0.5f * (rq.x + rk.x) + 0.5f * sgn * (rq.y - rk.y);
                float o1 = c[mi][ni][half * 2 + 1] + yqs[d + 1] + ykv.y
                         + 0.5f * (rq.z + rk.z) + 0.5f * sgn * (rq.w - rk.w);
                *(float2*)&ob[d] = make_float2(o0, o1);
            }
        }
    }
}

// ---------------- launcher ----------------
#define SUF_SMEM ((65 * 132 + 32 * 132 + 32 * 65) * 4)

extern "C" void kernel_launch(void* const* d_in, const int* in_sizes, int n_in,
                              void* d_out, int out_size) {
    const float* x      = (const float*)d_in[0];
    const float* w_rms  = (const float*)d_in[1];
    const float* W_q    = (const float*)d_in[2];
    const float* W_k    = (const float*)d_in[3];
    const float* W_pos  = (const float*)d_in[4];
    const float* b_pos  = (const float*)d_in[5];
    const float* qrb    = (const float*)d_in[6];
    const float* krb    = (const float*)d_in[7];
    const float* W_yq   = (const float*)d_in[8];
    const float* W_yk   = (const float*)d_in[9];
    const float* W_pair = (const float*)d_in[10];
    const float* b_pair = (const float*)d_in[11];
    float* out = (float*)d_out;

    float *qb, *kb, *yq, *yk, *TQ, *TK, *RQ, *RK, *Sb;
    __half *Xn, *Xg, *Ww, *Wy, *Qs, *Ks;
    int* f0;
    cudaGetSymbolAddress((void**)&qb, g_q);
    cudaGetSymbolAddress((void**)&kb, g_k);
    cudaGetSymbolAddress((void**)&yq, g_yq);
    cudaGetSymbolAddress((void**)&yk, g_yk);
    cudaGetSymbolAddress((void**)&TQ, g_TQ);
    cudaGetSymbolAddress((void**)&TK, g_TK);
    cudaGetSymbolAddress((void**)&RQ, g_RQ);
    cudaGetSymbolAddress((void**)&RK, g_RK);
    cudaGetSymbolAddress((void**)&Sb, g_S);
    cudaGetSymbolAddress((void**)&Xn, g_Xn);
    cudaGetSymbolAddress((void**)&Xg, g_Xg);
    cudaGetSymbolAddress((void**)&Ww, g_Ww);
    cudaGetSymbolAddress((void**)&Wy, g_Wy);
    cudaGetSymbolAddress((void**)&Qs, g_Qs);
    cudaGetSymbolAddress((void**)&Ks, g_Ks);
    cudaGetSymbolAddress((void**)&f0, g_f0);

    cudaFuncSetAttribute(k_proj, cudaFuncAttributeMaxDynamicSharedMemorySize, MMA_SMEM);
    cudaFuncSetAttribute(k_scores, cudaFuncAttributeMaxDynamicSharedMemorySize, MMA_SMEM);
    cudaFuncSetAttribute(k_suffix, cudaFuncAttributeMaxDynamicSharedMemorySize, SUF_SMEM);
    cudaFuncSetAttribute(k_pair2, cudaFuncAttributeMaxDynamicSharedMemorySize, P2_SMEM);

    k_pool<<<SP, 256>>>(x, w_rms, Xn, Xg);                                  // idx 0
    k_wsplit<<<dim3(2 * HD / 32, DIN / 32), 256>>>(W_yq, W_yk, HD, Wy);     // idx 1
    k_wsplit<<<dim3(2 * HDTOT / 32, DIN / 32), 256>>>(W_q, W_k, HDTOT, Ww); // idx 2
    k_proj<<<132, 256, MMA_SMEM>>>(Xn, Xg, Ww, Wy, qb, kb, yq, yk);         // idx 3 (profiled)
    k_f0<<<1, 512>>>(f0);                                                   // idx 4

    k_splitqk<<<SP * HDTOT / 256, 256>>>(qb, kb, Qs, Ks);

    dim3 gs(SP / 32, NH);
    k_suffix<<<gs, 256, SUF_SMEM>>>(qb, qrb, W_pos, b_pos, TQ);
    k_suffix<<<gs, 256, SUF_SMEM>>>(kb, krb, W_pos, b_pos, TK);
    k_fold<<<SP, 128>>>(TQ, TK, W_pair, RQ, RK);

    k_scores<<<dim3(4, 2, NH), 256, MMA_SMEM>>>(Qs, Ks, Sb);

    k_pair2<<<dim3(SP, 4), 256, P2_SMEM>>>(Sb, RQ, RK, f0, W_pair, b_pair, yq, yk, out);
}

// round 12
// speedup vs baseline: 1.1268x; 1.1268x over previous
#include <cuda_runtime.h>
#include <cuda_fp16.h>
#include <math.h>
#include <stdint.h>

#define SP    512
#define DIN   1536
#define NH    32
#define HD    128
#define HDTOT 4096
#define KS    3072   // 2*DIN  (fp16 2-term split)
#define KHS   256    // 2*HD

// ---------------- scratch ----------------
__device__ __half g_Xn[SP*KS];
__device__ __half g_Xg[SP*KS];
__device__ __half g_Ww[(size_t)2*HDTOT*KS];
__device__ __half g_Wy[2*HD*KS];
__device__ float g_q[SP*HDTOT];
__device__ float g_k[SP*HDTOT];
__device__ float g_yq[SP*HD];
__device__ float g_yk[SP*HD];
__device__ __half g_Qs[(size_t)NH*SP*KHS];
__device__ __half g_Ks[(size_t)NH*SP*KHS];
__device__ float g_S[(size_t)NH*SP*SP];
__device__ float g_TQ[33*SP*NH*2];
__device__ float g_TK[33*SP*NH*2];
__device__ float g_RQ[33*SP*HD*2];
__device__ float g_RK[33*SP*HD*2];
__device__ int   g_f0[SP];

// ---------------- helpers ----------------
__device__ __forceinline__ uint32_t smem_u32(const void* p) {
    uint32_t a;
    asm("{ .reg .u64 t; cvta.to.shared.u64 t, %1; cvt.u32.u64 %0, t; }" : "=r"(a) : "l"(p));
    return a;
}
__device__ __forceinline__ void cp16(uint32_t dst, const void* src) {
    asm volatile("cp.async.cg.shared.global [%0], [%1], 16;" :: "r"(dst), "l"(src));
}
#define CP_COMMIT() asm volatile("cp.async.commit_group;" ::: "memory")
#define CP_WAIT1()  asm volatile("cp.async.wait_group 1;" ::: "memory")

__device__ __forceinline__ void ldm_x4(uint32_t* r, uint32_t addr) {
    asm volatile("ldmatrix.sync.aligned.m8n8.x4.shared.b16 {%0,%1,%2,%3}, [%4];"
                 : "=r"(r[0]), "=r"(r[1]), "=r"(r[2]), "=r"(r[3]) : "r"(addr));
}
__device__ __forceinline__ void mma16816(float* c, const uint32_t* a, uint32_t b0, uint32_t b1) {
    asm volatile("mma.sync.aligned.m16n8k16.row.col.f32.f16.f16.f32 "
                 "{%0,%1,%2,%3}, {%4,%5,%6,%7}, {%8,%9}, {%0,%1,%2,%3};"
                 : "+f"(c[0]), "+f"(c[1]), "+f"(c[2]), "+f"(c[3])
                 : "r"(a[0]), "r"(a[1]), "r"(a[2]), "r"(a[3]), "r"(b0), "r"(b1));
}
__device__ __forceinline__ void split2h(float v, __half& hi, __half& lo) {
    hi = __float2half(v);
    lo = __float2half(v - __half2float(hi));
}

// BK=64: A tile 128x72 fp16 (144 B/row), B tile 256x72 fp16
#define A_TILE 18432
#define B_TILE 36864
#define STAGE_BYTES (A_TILE + B_TILE)
#define MMA_SMEM (3 * STAGE_BYTES)

__device__ __forceinline__ void mma_mainloop(
    uint32_t smb, const __half* __restrict__ Ab,
    const __half* __restrict__ Bb, int sA, int sB, int niter,
    int t, int lane, int wm, int wn, float c[4][8][4])
{
    uint32_t aoff[4], boff[4];
    {
        int lr = lane & 15, lc = lane >> 4;
        #pragma unroll
        for (int mi = 0; mi < 4; mi++) aoff[mi] = (wm * 64 + mi * 16 + lr) * 144 + lc * 16;
        #pragma unroll
        for (int nj = 0; nj < 4; nj++) boff[nj] = A_TILE + (wn * 64 + nj * 16 + lr) * 144 + lc * 16;
    }
    int lrow = t >> 3;
    int lc16 = (t & 7) * 16;
    int lcol_el = (t & 7) * 8;

    #pragma unroll
    for (int s = 0; s < 2; s++) {
        uint32_t db = smb + s * STAGE_BYTES;
        #pragma unroll
        for (int i = 0; i < 4; i++) {
            int row = lrow + i * 32;
            cp16(db + row * 144 + lc16, Ab + (size_t)row * sA + s * 64 + lcol_el);
        }
        #pragma unroll
        for (int i = 0; i < 8; i++) {
            int row = lrow + i * 32;
            cp16(db + A_TILE + row * 144 + lc16, Bb + (size_t)row * sB + s * 64 + lcol_el);
        }
        CP_COMMIT();
    }

    for (int ck = 0; ck < niter; ck++) {
        CP_WAIT1();
        __syncthreads();
        int pf = ck + 2;
        if (pf < niter) {
            uint32_t db = smb + (pf % 3) * STAGE_BYTES;
            #pragma unroll
            for (int i = 0; i < 4; i++) {
                int row = lrow + i * 32;
                cp16(db + row * 144 + lc16, Ab + (size_t)row * sA + pf * 64 + lcol_el);
            }
            #pragma unroll
            for (int i = 0; i < 8; i++) {
                int row = lrow + i * 32;
                cp16(db + A_TILE + row * 144 + lc16, Bb + (size_t)row * sB + pf * 64 + lcol_el);
            }
        }
        CP_COMMIT();
        uint32_t sa = smb + (ck % 3) * STAGE_BYTES;
        #pragma unroll
        for (int kk = 0; kk < 4; kk++) {
            uint32_t a[4][4], b[4][4];
            #pragma unroll
            for (int mi = 0; mi < 4; mi++) ldm_x4(a[mi], sa + aoff[mi] + kk * 32);
            #pragma unroll
            for (int nj = 0; nj < 4; nj++) ldm_x4(b[nj], sa + boff[nj] + kk * 32);
            #pragma unroll
            for (int mi = 0; mi < 4; mi++)
                #pragma unroll
                for (int ni = 0; ni < 8; ni++)
                    mma16816(c[mi][ni], a[mi], b[ni >> 1][ni & 1], b[ni >> 1][(ni & 1) + 2]);
        }
    }
}

// ---------------- K1: pool + rmsnorm + gelu -> fp16 [hi,lo] ----------------
__global__ void k_pool(const float* __restrict__ x, const float* __restrict__ w_rms,
                       __half* __restrict__ Xn, __half* __restrict__ Xg) {
    int sp = blockIdx.x;
    const float* xb = x + (size_t)sp * 16 * DIN;
    __shared__ float xp[DIN];
    __shared__ float red[256];
    int t = threadIdx.x;
    float ssq = 0.f;
    for (int c = t; c < DIN; c += 256) {
        float s = 0.f;
        #pragma unroll
        for (int r = 0; r < 16; r++) s += xb[r * DIN + c];
        s *= (1.f / 16.f);
        xp[c] = s;
        ssq += s * s;
    }
    red[t] = ssq;
    __syncthreads();
    for (int o = 128; o > 0; o >>= 1) {
        if (t < o) red[t] += red[t + o];
        __syncthreads();
    }
    float scale = rsqrtf(red[0] / (float)DIN + 1e-6f);
    size_t b = (size_t)sp * KS;
    for (int c = t; c < DIN; c += 256) {
        float v = xp[c] * scale * w_rms[c];
        __half hi, lo;
        split2h(v, hi, lo);
        Xn[b + c] = hi; Xn[b + DIN + c] = lo;
        float g = v * normcdff(v);
        split2h(g, hi, lo);
        Xg[b + c] = hi; Xg[b + DIN + c] = lo;
    }
}

// ---------------- K2: f0 table ----------------
__global__ void k_f0(int* __restrict__ f0) {
    int d = threadIdx.x;
    if (d < SP) {
        const float log_step = (float)(log(481.0) / 32.0);
        int cnt = 0;
        #pragma unroll
        for (int f = 0; f < 32; f++) {
            float cw = (float)f + expf((float)f * log_step);
            if (cw <= (float)d) cnt++;
        }
        f0[d] = cnt;
    }
}

// ---------------- K4: transpose weights -> fp16 [hi,hi] ----------------
__global__ void k_wsplit(const float* __restrict__ srcA, const float* __restrict__ srcB,
                         int Nsrc, __half* __restrict__ dst) {
    __shared__ float tile[32][33];
    int t = threadIdx.x;
    int n0 = blockIdx.x * 32, k0 = blockIdx.y * 32;
    const float* src = (n0 < Nsrc) ? srcA : srcB;
    int nb = (n0 < Nsrc) ? n0 : (n0 - Nsrc);
    #pragma unroll
    for (int i = 0; i < 4; i++) {
        int r = (t >> 5) + i * 8, c = t & 31;
        tile[r][c] = src[(size_t)(k0 + r) * Nsrc + nb + c];
    }
    __syncthreads();
    #pragma unroll
    for (int i = 0; i < 4; i++) {
        int rn = (t >> 5) + i * 8;
        int kk = k0 + (t & 31);
        __half hi = __float2half(tile[t & 31][rn]);
        size_t row = (size_t)(n0 + rn) * KS;
        dst[row + kk] = hi;
        dst[row + DIN + kk] = hi;
    }
}

// ---------------- K5: fused projection GEMM (CTA 128x256) ----------------
__global__ void __launch_bounds__(256) k_proj(
    const __half* __restrict__ Xn, const __half* __restrict__ Xg,
    const __half* __restrict__ Ww, const __half* __restrict__ Wy,
    float* __restrict__ q, float* __restrict__ k,
    float* __restrict__ yq, float* __restrict__ yk)
{
    extern __shared__ char sm[];
    uint32_t smb = smem_u32(sm);
    int t = threadIdx.x, w = t >> 5, lane = t & 31;
    int wm = w >> 2, wn = w & 3;
    int bid = blockIdx.x;
    int mt, nt;
    if (bid < 128) { mt = bid & 3; nt = bid >> 2; }
    else { mt = bid - 128; nt = 32; }

    const __half* Ab = (bid < 128) ? (Xn + (size_t)mt * 128 * KS)
                                   : (Xg + (size_t)mt * 128 * KS);
    const __half* Bb = (nt < 32) ? (Ww + (size_t)nt * 256 * KS) : Wy;

    float c[4][8][4];
    #pragma unroll
    for (int i = 0; i < 4; i++)
        #pragma unroll
        for (int j = 0; j < 8; j++)
            #pragma unroll
            for (int e = 0; e < 4; e++) c[i][j][e] = 0.f;

    mma_mainloop(smb, Ab, Bb, KS, KS, KS / 64, t, lane, wm, wn, c);

    int r0 = lane >> 2, c0 = (lane & 3) * 2;
    int srow0 = mt * 128;
    #pragma unroll
    for (int mi = 0; mi < 4; mi++) {
        #pragma unroll
        for (int ni = 0; ni < 8; ni++) {
            #pragma unroll
            for (int half = 0; half < 2; half++) {
                int s = srow0 + wm * 64 + mi * 16 + r0 + half * 8;
                int colL = wn * 64 + ni * 8 + c0;
                float2 fv = make_float2(c[mi][ni][half * 2], c[mi][ni][half * 2 + 1]);
                if (nt < 32) {
                    int col = nt * 256 + colL;
                    bool isQ = col < HDTOT;
                    float* o = isQ ? q : k;
                    int nn = isQ ? col : col - HDTOT;
                    *(float2*)&o[(size_t)s * HDTOT + nn] = fv;
                } else {
                    float* o = (colL < HD) ? yq : yk;
                    int nn = (colL < HD) ? colL : colL - HD;
                    *(float2*)&o[(size_t)s * HD + nn] = fv;
                }
            }
        }
    }
}

// ---------------- K5s: scores GEMM (CTA 128x256, batched over heads) ----------------
__global__ void __launch_bounds__(256) k_scores(
    const __half* __restrict__ Qs, const __half* __restrict__ Ks,
    float* __restrict__ S)
{
    extern __shared__ char sm[];
    uint32_t smb = smem_u32(sm);
    int t = threadIdx.x, w = t >> 5, lane = t & 31;
    int wm = w >> 2, wn = w & 3;
    int m0 = blockIdx.x * 128, n0 = blockIdx.y * 256, z = blockIdx.z;

    const __half* Ab = Qs + (size_t)z * SP * KHS + (size_t)m0 * KHS;
    const __half* Bb = Ks + (size_t)z * SP * KHS + (size_t)n0 * KHS;

    float c[4][8][4];
    #pragma unroll
    for (int i = 0; i < 4; i++)
        #pragma unroll
        for (int j = 0; j < 8; j++)
            #pragma unroll
            for (int e = 0; e < 4; e++) c[i][j][e] = 0.f;

    mma_mainloop(smb, Ab, Bb, KHS, KHS, KHS / 64, t, lane, wm, wn, c);

    int r0 = lane >> 2, c0 = (lane & 3) * 2;
    #pragma unroll
    for (int mi = 0; mi < 4; mi++) {
        #pragma unroll
        for (int ni = 0; ni < 8; ni++) {
            #pragma unroll
            for (int half = 0; half < 2; half++) {
                int row = m0 + wm * 64 + mi * 16 + r0 + half * 8;
                int col = n0 + wn * 64 + ni * 8 + c0;
                float2 fv = make_float2(c[mi][ni][half * 2], c[mi][ni][half * 2 + 1]);
                *(float2*)&S[((size_t)(z * SP + row)) * SP + col] = fv;
            }
        }
    }
}

// ---------------- K5b: coalesced split of q/k -> Qs/Ks ----------------
__global__ void k_splitqk(const float* __restrict__ q, const float* __restrict__ k,
                          __half* __restrict__ Qs, __half* __restrict__ Ks) {
    int idx = blockIdx.x * 256 + threadIdx.x;
    int s = idx >> 12, n = idx & 4095;
    int h = n >> 7, c = n & 127;
    size_t base = ((size_t)h * SP + s) * KHS + c;
    __half hi, lo;
    split2h(q[idx], hi, lo);
    Qs[base] = hi; Qs[base + HD] = lo;
    __half khi = __float2half(k[idx]);
    Ks[base] = khi; Ks[base + HD] = khi;
}

// ---------------- K6: suffix tables (merged TQ/TK via z) ----------------
__global__ void __launch_bounds__(256) k_suffix(const float* __restrict__ qk0,
                                                const float* __restrict__ qk1,
                                                const float* __restrict__ rb0,
                                                const float* __restrict__ rb1,
                                                const float* __restrict__ W_pos,
                                                const float* __restrict__ b_pos,
                                                float* __restrict__ T0,
                                                float* __restrict__ T1) {
    extern __shared__ float smf[];
    float* ws = smf;
    float* qs = ws + 65 * 132;
    float* Ms = qs + 32 * 132;
    int sel = blockIdx.z;
    const float* qk    = sel ? qk1 : qk0;
    const float* rbias = sel ? rb1 : rb0;
    float* T           = sel ? T1 : T0;
    int h = blockIdx.y;
    int q0 = blockIdx.x * 32;
    int t = threadIdx.x;
    for (int i = t; i < 65 * 128; i += 256) {
        int f = i >> 7, c = i & 127;
        ws[f * 132 + c] = (f < 64) ? W_pos[f * HDTOT + h * HD + c] : b_pos[h * HD + c];
    }
    for (int i = t; i < 32 * 128; i += 256) {
        int r = i >> 7, c = i & 127;
        qs[r * 132 + c] = qk[(size_t)(q0 + r) * HDTOT + h * HD + c] + rbias[h * HD + c];
    }
    __syncthreads();
    for (int i = t; i < 32 * 65; i += 256) {
        int r = i / 65, f = i % 65;
        const float4* qr = (const float4*)&qs[r * 132];
        const float4* wr = (const float4*)&ws[f * 132];
        float acc = 0.f;
        #pragma unroll
        for (int c4 = 0; c4 < 32; c4++) {
            float4 a = qr[c4], b = wr[c4];
            acc += a.x * b.x + a.y * b.y + a.z * b.z + a.w * b.w;
        }
        Ms[r * 65 + f] = acc;
    }
    __syncthreads();
    for (int i = t; i < 32 * 33; i += 256) {
        int r = i / 33, j = i % 33;
        float sa = Ms[r * 65 + 64];
        float sb = 0.f;
        for (int f = j; f < 32; f++) { sa += Ms[r * 65 + f]; sb += Ms[r * 65 + 32 + f]; }
        int q = q0 + r;
        T[((j * SP + q) * NH + h) * 2] = sa;
        T[((j * SP + q) * NH + h) * 2 + 1] = sb;
    }
}

// ---------------- K7: fold suffix tables through W_pair ----------------
__global__ void __launch_bounds__(128) k_fold(const float* __restrict__ TQ,
                                              const float* __restrict__ TK,
                                              const float* __restrict__ Wp,
                                              float* __restrict__ RQ,
                                              float* __restrict__ RK) {
    __shared__ float tq[33 * 64], tk[33 * 64];
    int q = blockIdx.x, t = threadIdx.x;
    for (int i = t; i < 33 * 64; i += 128) {
        int j = i >> 6, r = i & 63;
        tq[i] = TQ[((size_t)j * SP + q) * 64 + r];
        tk[i] = TK[((size_t)j * SP + q) * 64 + r];
    }
    float wcol[NH];
    #pragma unroll
    for (int h = 0; h < NH; h++) wcol[h] = Wp[h * HD + t];
    __syncthreads();
    for (int j = 0; j < 33; j++) {
        float aa = 0.f, ab = 0.f, ba = 0.f, bb = 0.f;
        const float* tqj = &tq[j * 64];
        const float* tkj = &tk[j * 64];
        #pragma unroll
        for (int h = 0; h < NH; h++) {
            float w = wcol[h];
            aa += tqj[2 * h] * w;  ab += tqj[2 * h + 1] * w;
            ba += tkj[2 * h] * w;  bb += tkj[2 * h + 1] * w;
        }
        size_t ob = ((size_t)j * SP + q) * 256 + t * 2;
        RQ[ob] = aa; RQ[ob + 1] = ab;
        RK[ob] = ba; RK[ob + 1] = bb;
    }
}

// ---------------- K8: final pass (FFMA2 packed fp32x2) ----------------
__global__ void __launch_bounds__(256) k_pair2(const float* __restrict__ S,
                                               const float* __restrict__ RQ,
                                               const float* __restrict__ RK,
                                               const int* __restrict__ f0tab,
                                               const float* __restrict__ Wp,
                                               const float* __restrict__ bp,
                                               const float* __restrict__ yq,
                                               const float* __restrict__ yk,
                                               float* __restrict__ out) {
    __shared__ __align__(16) float Sh[128 * 36];   // row stride 144 B (16B aligned)
    int t = threadIdx.x;
    int q = blockIdx.x, k0 = blockIdx.y * 128;
    for (int i = t; i < 4096; i += 256) {
        int h = i >> 7, kk = i & 127;
        Sh[kk * 36 + h] = S[(((size_t)h * SP + q) << 9) + k0 + kk];
    }
    int d = t & 127, g = t >> 7;
    // W_pair column packed into 16 f32x2 registers (adjacent h pairs)
    uint64_t w2[16];
    #pragma unroll
    for (int h2 = 0; h2 < 16; h2++) {
        float w0 = Wp[(2 * h2) * HD + d], w1 = Wp[(2 * h2 + 1) * HD + d];
        asm("mov.b64 %0, {%1,%2};" : "=l"(w2[h2]) : "f"(w0), "f"(w1));
    }
    float base0 = bp[d] + yq[q * HD + d];
    __syncthreads();
    for (int kk = g * 64; kk < g * 64 + 64; kk++) {
        int k = k0 + kk;
        int delta = k - q;
        int dd = delta >= 0 ? delta : -delta;
        float sgn = delta > 0 ? 1.f : (delta < 0 ? -1.f : 0.f);
        int j = f0tab[dd];
        float2 rq = *(const float2*)&RQ[((size_t)j * SP + q) * 256 + d * 2];
        float2 rk = *(const float2*)&RK[((size_t)j * SP + k) * 256 + d * 2];
        float base = base0 + yk[k * HD + d]
                   + 0.5f * (rq.x + rk.x) + 0.5f * sgn * (rq.y - rk.y);
        const ulonglong2* sr2 = (const ulonglong2*)&Sh[kk * 36];
        uint64_t acc2 = 0;   // packed {0.f, 0.f}
        #pragma unroll
        for (int h8 = 0; h8 < 8; h8++) {
            ulonglong2 v = sr2[h8];   // 4 S values as two packed f32x2
            asm("fma.rn.f32x2 %0, %1, %2, %0;" : "+l"(acc2) : "l"(v.x), "l"(w2[h8 * 2]));
            asm("fma.rn.f32x2 %0, %1, %2, %0;" : "+l"(acc2) : "l"(v.y), "l"(w2[h8 * 2 + 1]));
        }
        float lo, hi;
        asm("mov.b64 {%0,%1}, %2;" : "=f"(lo), "=f"(hi) : "l"(acc2));
        out[((size_t)(q * SP + k)) * HD + d] = base + lo + hi;
    }
}

// ---------------- launcher ----------------
#define SUF_SMEM ((65 * 132 + 32 * 132 + 32 * 65) * 4)

extern "C" void kernel_launch(void* const* d_in, const int* in_sizes, int n_in,
                              void* d_out, int out_size) {
    const float* x      = (const float*)d_in[0];
    const float* w_rms  = (const float*)d_in[1];
    const float* W_q    = (const float*)d_in[2];
    const float* W_k    = (const float*)d_in[3];
    const float* W_pos  = (const float*)d_in[4];
    const float* b_pos  = (const float*)d_in[5];
    const float* qrb    = (const float*)d_in[6];
    const float* krb    = (const float*)d_in[7];
    const float* W_yq   = (const float*)d_in[8];
    const float* W_yk   = (const float*)d_in[9];
    const float* W_pair = (const float*)d_in[10];
    const float* b_pair = (const float*)d_in[11];
    float* out = (float*)d_out;

    float *qb, *kb, *yq, *yk, *TQ, *TK, *RQ, *RK, *Sb;
    __half *Xn, *Xg, *Ww, *Wy, *Qs, *Ks;
    int* f0;
    cudaGetSymbolAddress((void**)&qb, g_q);
    cudaGetSymbolAddress((void**)&kb, g_k);
    cudaGetSymbolAddress((void**)&yq, g_yq);
    cudaGetSymbolAddress((void**)&yk, g_yk);
    cudaGetSymbolAddress((void**)&TQ, g_TQ);
    cudaGetSymbolAddress((void**)&TK, g_TK);
    cudaGetSymbolAddress((void**)&RQ, g_RQ);
    cudaGetSymbolAddress((void**)&RK, g_RK);
    cudaGetSymbolAddress((void**)&Sb, g_S);
    cudaGetSymbolAddress((void**)&Xn, g_Xn);
    cudaGetSymbolAddress((void**)&Xg, g_Xg);
    cudaGetSymbolAddress((void**)&Ww, g_Ww);
    cudaGetSymbolAddress((void**)&Wy, g_Wy);
    cudaGetSymbolAddress((void**)&Qs, g_Qs);
    cudaGetSymbolAddress((void**)&Ks, g_Ks);
    cudaGetSymbolAddress((void**)&f0, g_f0);

    cudaFuncSetAttribute(k_proj, cudaFuncAttributeMaxDynamicSharedMemorySize, MMA_SMEM);
    cudaFuncSetAttribute(k_scores, cudaFuncAttributeMaxDynamicSharedMemorySize, MMA_SMEM);
    cudaFuncSetAttribute(k_suffix, cudaFuncAttributeMaxDynamicSharedMemorySize, SUF_SMEM);

    k_pool<<<SP, 256>>>(x, w_rms, Xn, Xg);                                  // idx 0
    k_wsplit<<<dim3(2 * HD / 32, DIN / 32), 256>>>(W_yq, W_yk, HD, Wy);     // idx 1
    k_wsplit<<<dim3(2 * HDTOT / 32, DIN / 32), 256>>>(W_q, W_k, HDTOT, Ww); // idx 2
    k_proj<<<132, 256, MMA_SMEM>>>(Xn, Xg, Ww, Wy, qb, kb, yq, yk);         // idx 3 (profiled)
    k_f0<<<1, 512>>>(f0);                                                   // idx 4

    k_splitqk<<<SP * HDTOT / 256, 256>>>(qb, kb, Qs, Ks);

    dim3 gs(SP / 32, NH, 2);
    k_suffix<<<gs, 256, SUF_SMEM>>>(qb, kb, qrb, krb, W_pos, b_pos, TQ, TK);
    k_fold<<<SP, 128>>>(TQ, TK, W_pair, RQ, RK);

    k_scores<<<dim3(4, 2, NH), 256, MMA_SMEM>>>(Qs, Ks, Sb);

    k_pair2<<<dim3(SP, 4), 256>>>(Sb, RQ, RK, f0, W_pair, b_pair, yq, yk, out);
}

// round 13
// speedup vs baseline: 1.1402x; 1.0119x over previous
#include <cuda_runtime.h>
#include <cuda_fp16.h>
#include <math.h>
#include <stdint.h>

#define SP    512
#define DIN   1536
#define NH    32
#define HD    128
#define HDTOT 4096
#define KS    3072   // 2*DIN  (fp16 2-term split)
#define KHS   256    // 2*HD

// ---------------- scratch ----------------
__device__ __half g_Xn[SP*KS];
__device__ __half g_Xg[SP*KS];
__device__ __half g_Ww[(size_t)2*HDTOT*KS];
__device__ __half g_Wy[2*HD*KS];
__device__ float g_q[SP*HDTOT];
__device__ float g_k[SP*HDTOT];
__device__ float g_yq[SP*HD];
__device__ float g_yk[SP*HD];
__device__ __half g_Qs[(size_t)NH*SP*KHS];
__device__ __half g_Ks[(size_t)NH*SP*KHS];
__device__ float g_S[(size_t)NH*SP*SP];
__device__ float g_TQ[33*SP*NH*2];
__device__ float g_TK[33*SP*NH*2];
__device__ float g_RQ[33*SP*HD*2];
__device__ float g_RK[33*SP*HD*2];
__device__ int   g_f0[SP];

// ---------------- helpers ----------------
__device__ __forceinline__ uint32_t smem_u32(const void* p) {
    uint32_t a;
    asm("{ .reg .u64 t; cvta.to.shared.u64 t, %1; cvt.u32.u64 %0, t; }" : "=r"(a) : "l"(p));
    return a;
}
__device__ __forceinline__ void cp16(uint32_t dst, const void* src) {
    asm volatile("cp.async.cg.shared.global [%0], [%1], 16;" :: "r"(dst), "l"(src));
}
#define CP_COMMIT() asm volatile("cp.async.commit_group;" ::: "memory")
#define CP_WAIT1()  asm volatile("cp.async.wait_group 1;" ::: "memory")

__device__ __forceinline__ void ldm_x4(uint32_t* r, uint32_t addr) {
    asm volatile("ldmatrix.sync.aligned.m8n8.x4.shared.b16 {%0,%1,%2,%3}, [%4];"
                 : "=r"(r[0]), "=r"(r[1]), "=r"(r[2]), "=r"(r[3]) : "r"(addr));
}
__device__ __forceinline__ void mma16816(float* c, const uint32_t* a, uint32_t b0, uint32_t b1) {
    asm volatile("mma.sync.aligned.m16n8k16.row.col.f32.f16.f16.f32 "
                 "{%0,%1,%2,%3}, {%4,%5,%6,%7}, {%8,%9}, {%0,%1,%2,%3};"
                 : "+f"(c[0]), "+f"(c[1]), "+f"(c[2]), "+f"(c[3])
                 : "r"(a[0]), "r"(a[1]), "r"(a[2]), "r"(a[3]), "r"(b0), "r"(b1));
}
__device__ __forceinline__ void split2h(float v, __half& hi, __half& lo) {
    hi = __float2half(v);
    lo = __float2half(v - __half2float(hi));
}

// BK=64: A tile 128x72 fp16 (144 B/row), B tile 256x72 fp16
#define A_TILE 18432
#define B_TILE 36864
#define STAGE_BYTES (A_TILE + B_TILE)
#define MMA_SMEM (3 * STAGE_BYTES)

__device__ __forceinline__ void mma_mainloop(
    uint32_t smb, const __half* __restrict__ Ab,
    const __half* __restrict__ Bb, int sA, int sB, int niter,
    int t, int lane, int wm, int wn, float c[4][8][4])
{
    uint32_t aoff[4], boff[4];
    {
        int lr = lane & 15, lc = lane >> 4;
        #pragma unroll
        for (int mi = 0; mi < 4; mi++) aoff[mi] = (wm * 64 + mi * 16 + lr) * 144 + lc * 16;
        #pragma unroll
        for (int nj = 0; nj < 4; nj++) boff[nj] = A_TILE + (wn * 64 + nj * 16 + lr) * 144 + lc * 16;
    }
    int lrow = t >> 3;
    int lc16 = (t & 7) * 16;
    int lcol_el = (t & 7) * 8;

    #pragma unroll
    for (int s = 0; s < 2; s++) {
        uint32_t db = smb + s * STAGE_BYTES;
        #pragma unroll
        for (int i = 0; i < 4; i++) {
            int row = lrow + i * 32;
            cp16(db + row * 144 + lc16, Ab + (size_t)row * sA + s * 64 + lcol_el);
        }
        #pragma unroll
        for (int i = 0; i < 8; i++) {
            int row = lrow + i * 32;
            cp16(db + A_TILE + row * 144 + lc16, Bb + (size_t)row * sB + s * 64 + lcol_el);
        }
        CP_COMMIT();
    }

    for (int ck = 0; ck < niter; ck++) {
        CP_WAIT1();
        __syncthreads();
        int pf = ck + 2;
        if (pf < niter) {
            uint32_t db = smb + (pf % 3) * STAGE_BYTES;
            #pragma unroll
            for (int i = 0; i < 4; i++) {
                int row = lrow + i * 32;
                cp16(db + row * 144 + lc16, Ab + (size_t)row * sA + pf * 64 + lcol_el);
            }
            #pragma unroll
            for (int i = 0; i < 8; i++) {
                int row = lrow + i * 32;
                cp16(db + A_TILE + row * 144 + lc16, Bb + (size_t)row * sB + pf * 64 + lcol_el);
            }
        }
        CP_COMMIT();
        uint32_t sa = smb + (ck % 3) * STAGE_BYTES;
        #pragma unroll
        for (int kk = 0; kk < 4; kk++) {
            uint32_t a[4][4], b[4][4];
            #pragma unroll
            for (int mi = 0; mi < 4; mi++) ldm_x4(a[mi], sa + aoff[mi] + kk * 32);
            #pragma unroll
            for (int nj = 0; nj < 4; nj++) ldm_x4(b[nj], sa + boff[nj] + kk * 32);
            #pragma unroll
            for (int mi = 0; mi < 4; mi++)
                #pragma unroll
                for (int ni = 0; ni < 8; ni++)
                    mma16816(c[mi][ni], a[mi], b[ni >> 1][ni & 1], b[ni >> 1][(ni & 1) + 2]);
        }
    }
}

// ---------------- K1: pool + rmsnorm + gelu -> fp16 [hi,lo] ----------------
__global__ void k_pool(const float* __restrict__ x, const float* __restrict__ w_rms,
                       __half* __restrict__ Xn, __half* __restrict__ Xg) {
    int sp = blockIdx.x;
    const float* xb = x + (size_t)sp * 16 * DIN;
    __shared__ float xp[DIN];
    __shared__ float red[256];
    int t = threadIdx.x;
    float ssq = 0.f;
    for (int c = t; c < DIN; c += 256) {
        float s = 0.f;
        #pragma unroll
        for (int r = 0; r < 16; r++) s += xb[r * DIN + c];
        s *= (1.f / 16.f);
        xp[c] = s;
        ssq += s * s;
    }
    red[t] = ssq;
    __syncthreads();
    for (int o = 128; o > 0; o >>= 1) {
        if (t < o) red[t] += red[t + o];
        __syncthreads();
    }
    float scale = rsqrtf(red[0] / (float)DIN + 1e-6f);
    size_t b = (size_t)sp * KS;
    for (int c = t; c < DIN; c += 256) {
        float v = xp[c] * scale * w_rms[c];
        __half hi, lo;
        split2h(v, hi, lo);
        Xn[b + c] = hi; Xn[b + DIN + c] = lo;
        float g = v * normcdff(v);
        split2h(g, hi, lo);
        Xg[b + c] = hi; Xg[b + DIN + c] = lo;
    }
}

// ---------------- K2: f0 table ----------------
__global__ void k_f0(int* __restrict__ f0) {
    int d = threadIdx.x;
    if (d < SP) {
        const float log_step = (float)(log(481.0) / 32.0);
        int cnt = 0;
        #pragma unroll
        for (int f = 0; f < 32; f++) {
            float cw = (float)f + expf((float)f * log_step);
            if (cw <= (float)d) cnt++;
        }
        f0[d] = cnt;
    }
}

// ---------------- K4: transpose weights -> fp16 [hi,hi] ----------------
__global__ void k_wsplit(const float* __restrict__ srcA, const float* __restrict__ srcB,
                         int Nsrc, __half* __restrict__ dst) {
    __shared__ float tile[32][33];
    int t = threadIdx.x;
    int n0 = blockIdx.x * 32, k0 = blockIdx.y * 32;
    const float* src = (n0 < Nsrc) ? srcA : srcB;
    int nb = (n0 < Nsrc) ? n0 : (n0 - Nsrc);
    #pragma unroll
    for (int i = 0; i < 4; i++) {
        int r = (t >> 5) + i * 8, c = t & 31;
        tile[r][c] = src[(size_t)(k0 + r) * Nsrc + nb + c];
    }
    __syncthreads();
    #pragma unroll
    for (int i = 0; i < 4; i++) {
        int rn = (t >> 5) + i * 8;
        int kk = k0 + (t & 31);
        __half hi = __float2half(tile[t & 31][rn]);
        size_t row = (size_t)(n0 + rn) * KS;
        dst[row + kk] = hi;
        dst[row + DIN + kk] = hi;
    }
}

// ---------------- K5: fused projection GEMM (CTA 128x256) ----------------
__global__ void __launch_bounds__(256) k_proj(
    const __half* __restrict__ Xn, const __half* __restrict__ Xg,
    const __half* __restrict__ Ww, const __half* __restrict__ Wy,
    float* __restrict__ q, float* __restrict__ k,
    float* __restrict__ yq, float* __restrict__ yk)
{
    extern __shared__ char sm[];
    uint32_t smb = smem_u32(sm);
    int t = threadIdx.x, w = t >> 5, lane = t & 31;
    int wm = w >> 2, wn = w & 3;
    int bid = blockIdx.x;
    int mt, nt;
    if (bid < 128) { mt = bid & 3; nt = bid >> 2; }
    else { mt = bid - 128; nt = 32; }

    const __half* Ab = (bid < 128) ? (Xn + (size_t)mt * 128 * KS)
                                   : (Xg + (size_t)mt * 128 * KS);
    const __half* Bb = (nt < 32) ? (Ww + (size_t)nt * 256 * KS) : Wy;

    float c[4][8][4];
    #pragma unroll
    for (int i = 0; i < 4; i++)
        #pragma unroll
        for (int j = 0; j < 8; j++)
            #pragma unroll
            for (int e = 0; e < 4; e++) c[i][j][e] = 0.f;

    mma_mainloop(smb, Ab, Bb, KS, KS, KS / 64, t, lane, wm, wn, c);

    int r0 = lane >> 2, c0 = (lane & 3) * 2;
    int srow0 = mt * 128;
    #pragma unroll
    for (int mi = 0; mi < 4; mi++) {
        #pragma unroll
        for (int ni = 0; ni < 8; ni++) {
            #pragma unroll
            for (int half = 0; half < 2; half++) {
                int s = srow0 + wm * 64 + mi * 16 + r0 + half * 8;
                int colL = wn * 64 + ni * 8 + c0;
                float2 fv = make_float2(c[mi][ni][half * 2], c[mi][ni][half * 2 + 1]);
                if (nt < 32) {
                    int col = nt * 256 + colL;
                    bool isQ = col < HDTOT;
                    float* o = isQ ? q : k;
                    int nn = isQ ? col : col - HDTOT;
                    *(float2*)&o[(size_t)s * HDTOT + nn] = fv;
                } else {
                    float* o = (colL < HD) ? yq : yk;
                    int nn = (colL < HD) ? colL : colL - HD;
                    *(float2*)&o[(size_t)s * HD + nn] = fv;
                }
            }
        }
    }
}

// ---------------- K5s: scores GEMM (CTA 128x256, batched over heads) ----------------
__global__ void __launch_bounds__(256) k_scores(
    const __half* __restrict__ Qs, const __half* __restrict__ Ks,
    float* __restrict__ S)
{
    extern __shared__ char sm[];
    uint32_t smb = smem_u32(sm);
    int t = threadIdx.x, w = t >> 5, lane = t & 31;
    int wm = w >> 2, wn = w & 3;
    int m0 = blockIdx.x * 128, n0 = blockIdx.y * 256, z = blockIdx.z;

    const __half* Ab = Qs + (size_t)z * SP * KHS + (size_t)m0 * KHS;
    const __half* Bb = Ks + (size_t)z * SP * KHS + (size_t)n0 * KHS;

    float c[4][8][4];
    #pragma unroll
    for (int i = 0; i < 4; i++)
        #pragma unroll
        for (int j = 0; j < 8; j++)
            #pragma unroll
            for (int e = 0; e < 4; e++) c[i][j][e] = 0.f;

    mma_mainloop(smb, Ab, Bb, KHS, KHS, KHS / 64, t, lane, wm, wn, c);

    int r0 = lane >> 2, c0 = (lane & 3) * 2;
    #pragma unroll
    for (int mi = 0; mi < 4; mi++) {
        #pragma unroll
        for (int ni = 0; ni < 8; ni++) {
            #pragma unroll
            for (int half = 0; half < 2; half++) {
                int row = m0 + wm * 64 + mi * 16 + r0 + half * 8;
                int col = n0 + wn * 64 + ni * 8 + c0;
                float2 fv = make_float2(c[mi][ni][half * 2], c[mi][ni][half * 2 + 1]);
                *(float2*)&S[((size_t)(z * SP + row)) * SP + col] = fv;
            }
        }
    }
}

// ---------------- K5b: coalesced split of q/k -> Qs/Ks ----------------
__global__ void k_splitqk(const float* __restrict__ q, const float* __restrict__ k,
                          __half* __restrict__ Qs, __half* __restrict__ Ks) {
    int idx = blockIdx.x * 256 + threadIdx.x;
    int s = idx >> 12, n = idx & 4095;
    int h = n >> 7, c = n & 127;
    size_t base = ((size_t)h * SP + s) * KHS + c;
    __half hi, lo;
    split2h(q[idx], hi, lo);
    Qs[base] = hi; Qs[base + HD] = lo;
    __half khi = __float2half(k[idx]);
    Ks[base] = khi; Ks[base + HD] = khi;
}

// ---------------- K6: suffix tables (merged TQ/TK via z) ----------------
__global__ void __launch_bounds__(256) k_suffix(const float* __restrict__ qk0,
                                                const float* __restrict__ qk1,
                                                const float* __restrict__ rb0,
                                                const float* __restrict__ rb1,
                                                const float* __restrict__ W_pos,
                                                const float* __restrict__ b_pos,
                                                float* __restrict__ T0,
                                                float* __restrict__ T1) {
    extern __shared__ float smf[];
    float* ws = smf;
    float* qs = ws + 65 * 132;
    float* Ms = qs + 32 * 132;
    int sel = blockIdx.z;
    const float* qk    = sel ? qk1 : qk0;
    const float* rbias = sel ? rb1 : rb0;
    float* T           = sel ? T1 : T0;
    int h = blockIdx.y;
    int q0 = blockIdx.x * 32;
    int t = threadIdx.x;
    for (int i = t; i < 65 * 128; i += 256) {
        int f = i >> 7, c = i & 127;
        ws[f * 132 + c] = (f < 64) ? W_pos[f * HDTOT + h * HD + c] : b_pos[h * HD + c];
    }
    for (int i = t; i < 32 * 128; i += 256) {
        int r = i >> 7, c = i & 127;
        qs[r * 132 + c] = qk[(size_t)(q0 + r) * HDTOT + h * HD + c] + rbias[h * HD + c];
    }
    __syncthreads();
    for (int i = t; i < 32 * 65; i += 256) {
        int r = i / 65, f = i % 65;
        const float4* qr = (const float4*)&qs[r * 132];
        const float4* wr = (const float4*)&ws[f * 132];
        float acc = 0.f;
        #pragma unroll
        for (int c4 = 0; c4 < 32; c4++) {
            float4 a = qr[c4], b = wr[c4];
            acc += a.x * b.x + a.y * b.y + a.z * b.z + a.w * b.w;
        }
        Ms[r * 65 + f] = acc;
    }
    __syncthreads();
    for (int i = t; i < 32 * 33; i += 256) {
        int r = i / 33, j = i % 33;
        float sa = Ms[r * 65 + 64];
        float sb = 0.f;
        for (int f = j; f < 32; f++) { sa += Ms[r * 65 + f]; sb += Ms[r * 65 + 32 + f]; }
        int q = q0 + r;
        T[((j * SP + q) * NH + h) * 2] = sa;
        T[((j * SP + q) * NH + h) * 2 + 1] = sb;
    }
}

// ---------------- K7: fold suffix tables through W_pair ----------------
__global__ void __launch_bounds__(128) k_fold(const float* __restrict__ TQ,
                                              const float* __restrict__ TK,
                                              const float* __restrict__ Wp,
                                              float* __restrict__ RQ,
                                              float* __restrict__ RK) {
    __shared__ float tq[33 * 64], tk[33 * 64];
    int q = blockIdx.x, t = threadIdx.x;
    for (int i = t; i < 33 * 64; i += 128) {
        int j = i >> 6, r = i & 63;
        tq[i] = TQ[((size_t)j * SP + q) * 64 + r];
        tk[i] = TK[((size_t)j * SP + q) * 64 + r];
    }
    float wcol[NH];
    #pragma unroll
    for (int h = 0; h < NH; h++) wcol[h] = Wp[h * HD + t];
    __syncthreads();
    for (int j = 0; j < 33; j++) {
        float aa = 0.f, ab = 0.f, ba = 0.f, bb = 0.f;
        const float* tqj = &tq[j * 64];
        const float* tkj = &tk[j * 64];
        #pragma unroll
        for (int h = 0; h < NH; h++) {
            float w = wcol[h];
            aa += tqj[2 * h] * w;  ab += tqj[2 * h + 1] * w;
            ba += tkj[2 * h] * w;  bb += tkj[2 * h + 1] * w;
        }
        size_t ob = ((size_t)j * SP + q) * 256 + t * 2;
        RQ[ob] = aa; RQ[ob + 1] = ab;
        RK[ob] = ba; RK[ob + 1] = bb;
    }
}

// ---------------- K8: final pass (FFMA2 packed fp32x2) ----------------
__global__ void __launch_bounds__(256) k_pair2(const float* __restrict__ S,
                                               const float* __restrict__ RQ,
                                               const float* __restrict__ RK,
                                               const int* __restrict__ f0tab,
                                               const float* __restrict__ Wp,
                                               const float* __restrict__ bp,
                                               const float* __restrict__ yq,
                                               const float* __restrict__ yk,
                                               float* __restrict__ out) {
    __shared__ __align__(16) float Sh[128 * 36];
    int t = threadIdx.x;
    int q = blockIdx.x, k0 = blockIdx.y * 128;
    for (int i = t; i < 4096; i += 256) {
        int h = i >> 7, kk = i & 127;
        Sh[kk * 36 + h] = S[(((size_t)h * SP + q) << 9) + k0 + kk];
    }
    int d = t & 127, g = t >> 7;
    uint64_t w2[16];
    #pragma unroll
    for (int h2 = 0; h2 < 16; h2++) {
        float w0 = Wp[(2 * h2) * HD + d], w1 = Wp[(2 * h2 + 1) * HD + d];
        asm("mov.b64 %0, {%1,%2};" : "=l"(w2[h2]) : "f"(w0), "f"(w1));
    }
    float base0 = bp[d] + yq[q * HD + d];
    __syncthreads();
    for (int kk = g * 64; kk < g * 64 + 64; kk++) {
        int k = k0 + kk;
        int delta = k - q;
        int dd = delta >= 0 ? delta : -delta;
        float sgn = delta > 0 ? 1.f : (delta < 0 ? -1.f : 0.f);
        int j = f0tab[dd];
        float2 rq = *(const float2*)&RQ[((size_t)j * SP + q) * 256 + d * 2];
        float2 rk = *(const float2*)&RK[((size_t)j * SP + k) * 256 + d * 2];
        float base = base0 + yk[k * HD + d]
                   + 0.5f * (rq.x + rk.x) + 0.5f * sgn * (rq.y - rk.y);
        const ulonglong2* sr2 = (const ulonglong2*)&Sh[kk * 36];
        uint64_t acc2 = 0;
        #pragma unroll
        for (int h8 = 0; h8 < 8; h8++) {
            ulonglong2 v = sr2[h8];
            asm("fma.rn.f32x2 %0, %1, %2, %0;" : "+l"(acc2) : "l"(v.x), "l"(w2[h8 * 2]));
            asm("fma.rn.f32x2 %0, %1, %2, %0;" : "+l"(acc2) : "l"(v.y), "l"(w2[h8 * 2 + 1]));
        }
        float lo, hi;
        asm("mov.b64 {%0,%1}, %2;" : "=f"(lo), "=f"(hi) : "l"(acc2));
        out[((size_t)(q * SP + k)) * HD + d] = base + lo + hi;
    }
}

// ---------------- launcher with stream-fork overlap ----------------
#define SUF_SMEM ((65 * 132 + 32 * 132 + 32 * 65) * 4)

extern "C" void kernel_launch(void* const* d_in, const int* in_sizes, int n_in,
                              void* d_out, int out_size) {
    const float* x      = (const float*)d_in[0];
    const float* w_rms  = (const float*)d_in[1];
    const float* W_q    = (const float*)d_in[2];
    const float* W_k    = (const float*)d_in[3];
    const float* W_pos  = (const float*)d_in[4];
    const float* b_pos  = (const float*)d_in[5];
    const float* qrb    = (const float*)d_in[6];
    const float* krb    = (const float*)d_in[7];
    const float* W_yq   = (const float*)d_in[8];
    const float* W_yk   = (const float*)d_in[9];
    const float* W_pair = (const float*)d_in[10];
    const float* b_pair = (const float*)d_in[11];
    float* out = (float*)d_out;

    float *qb, *kb, *yq, *yk, *TQ, *TK, *RQ, *RK, *Sb;
    __half *Xn, *Xg, *Ww, *Wy, *Qs, *Ks;
    int* f0;
    cudaGetSymbolAddress((void**)&qb, g_q);
    cudaGetSymbolAddress((void**)&kb, g_k);
    cudaGetSymbolAddress((void**)&yq, g_yq);
    cudaGetSymbolAddress((void**)&yk, g_yk);
    cudaGetSymbolAddress((void**)&TQ, g_TQ);
    cudaGetSymbolAddress((void**)&TK, g_TK);
    cudaGetSymbolAddress((void**)&RQ, g_RQ);
    cudaGetSymbolAddress((void**)&RK, g_RK);
    cudaGetSymbolAddress((void**)&Sb, g_S);
    cudaGetSymbolAddress((void**)&Xn, g_Xn);
    cudaGetSymbolAddress((void**)&Xg, g_Xg);
    cudaGetSymbolAddress((void**)&Ww, g_Ww);
    cudaGetSymbolAddress((void**)&Wy, g_Wy);
    cudaGetSymbolAddress((void**)&Qs, g_Qs);
    cudaGetSymbolAddress((void**)&Ks, g_Ks);
    cudaGetSymbolAddress((void**)&f0, g_f0);

    cudaFuncSetAttribute(k_proj, cudaFuncAttributeMaxDynamicSharedMemorySize, MMA_SMEM);
    cudaFuncSetAttribute(k_scores, cudaFuncAttributeMaxDynamicSharedMemorySize, MMA_SMEM);
    cudaFuncSetAttribute(k_suffix, cudaFuncAttributeMaxDynamicSharedMemorySize, SUF_SMEM);

    cudaStream_t s1;
    cudaStreamCreateWithFlags(&s1, cudaStreamNonBlocking);
    cudaEvent_t e0, e1, e2, e3;
    cudaEventCreateWithFlags(&e0, cudaEventDisableTiming);
    cudaEventCreateWithFlags(&e1, cudaEventDisableTiming);
    cudaEventCreateWithFlags(&e2, cudaEventDisableTiming);
    cudaEventCreateWithFlags(&e3, cudaEventDisableTiming);

    // fork 1: weight prep on s1, activation prep on default
    cudaEventRecord(e0, 0);
    cudaStreamWaitEvent(s1, e0, 0);
    k_wsplit<<<dim3(2 * HD / 32, DIN / 32), 256, 0, s1>>>(W_yq, W_yk, HD, Wy);
    k_wsplit<<<dim3(2 * HDTOT / 32, DIN / 32), 256, 0, s1>>>(W_q, W_k, HDTOT, Ww);
    cudaEventRecord(e1, s1);

    k_pool<<<SP, 256>>>(x, w_rms, Xn, Xg);
    k_f0<<<1, 512>>>(f0);

    // join -> proj
    cudaStreamWaitEvent(0, e1, 0);
    k_proj<<<132, 256, MMA_SMEM>>>(Xn, Xg, Ww, Wy, qb, kb, yq, yk);

    // fork 2: suffix+fold on s1, splitqk+scores on default
    cudaEventRecord(e2, 0);
    cudaStreamWaitEvent(s1, e2, 0);
    dim3 gs(SP / 32, NH, 2);
    k_suffix<<<gs, 256, SUF_SMEM, s1>>>(qb, kb, qrb, krb, W_pos, b_pos, TQ, TK);
    k_fold<<<SP, 128, 0, s1>>>(TQ, TK, W_pair, RQ, RK);
    cudaEventRecord(e3, s1);

    k_splitqk<<<SP * HDTOT / 256, 256>>>(qb, kb, Qs, Ks);
    k_scores<<<dim3(4, 2, NH), 256, MMA_SMEM>>>(Qs, Ks, Sb);

    // join -> pair2
    cudaStreamWaitEvent(0, e3, 0);
    k_pair2<<<dim3(SP, 4), 256>>>(Sb, RQ, RK, f0, W_pair, b_pair, yq, yk, out);

    cudaEventDestroy(e0);
    cudaEventDestroy(e1);
    cudaEventDestroy(e2);
    cudaEventDestroy(e3);
    cudaStreamDestroy(s1);
}

// round 14
// speedup vs baseline: 1.1439x; 1.0033x over previous
#include <cuda_runtime.h>
#include <cuda_fp16.h>
#include <math.h>
#include <stdint.h>

#define SP    512
#define DIN   1536
#define NH    32
#define HD    128
#define HDTOT 4096
#define KS    3072   // 2*DIN  (fp16 2-term split)

// ---------------- scratch ----------------
__device__ __half g_Xn[SP*KS];
__device__ __half g_Xg[SP*KS];
__device__ __half g_Ww[(size_t)2*HDTOT*KS];
__device__ __half g_Wy[2*HD*KS];
__device__ float g_q[SP*HDTOT];
__device__ float g_k[SP*HDTOT];
__device__ float g_yq[SP*HD];
__device__ float g_yk[SP*HD];
__device__ float g_S[(size_t)NH*SP*SP];
__device__ float g_TQ[33*SP*NH*2];
__device__ float g_TK[33*SP*NH*2];
__device__ float g_RQ[33*SP*HD*2];
__device__ float g_RK[33*SP*HD*2];
__device__ int   g_f0[SP];

// ---------------- helpers ----------------
__device__ __forceinline__ uint32_t smem_u32(const void* p) {
    uint32_t a;
    asm("{ .reg .u64 t; cvta.to.shared.u64 t, %1; cvt.u32.u64 %0, t; }" : "=r"(a) : "l"(p));
    return a;
}
__device__ __forceinline__ void cp16(uint32_t dst, const void* src) {
    asm volatile("cp.async.cg.shared.global [%0], [%1], 16;" :: "r"(dst), "l"(src));
}
#define CP_COMMIT() asm volatile("cp.async.commit_group;" ::: "memory")
#define CP_WAIT1()  asm volatile("cp.async.wait_group 1;" ::: "memory")

__device__ __forceinline__ void ldm_x4(uint32_t* r, uint32_t addr) {
    asm volatile("ldmatrix.sync.aligned.m8n8.x4.shared.b16 {%0,%1,%2,%3}, [%4];"
                 : "=r"(r[0]), "=r"(r[1]), "=r"(r[2]), "=r"(r[3]) : "r"(addr));
}
__device__ __forceinline__ void mma16816(float* c, const uint32_t* a, uint32_t b0, uint32_t b1) {
    asm volatile("mma.sync.aligned.m16n8k16.row.col.f32.f16.f16.f32 "
                 "{%0,%1,%2,%3}, {%4,%5,%6,%7}, {%8,%9}, {%0,%1,%2,%3};"
                 : "+f"(c[0]), "+f"(c[1]), "+f"(c[2]), "+f"(c[3])
                 : "r"(a[0]), "r"(a[1]), "r"(a[2]), "r"(a[3]), "r"(b0), "r"(b1));
}
__device__ __forceinline__ void split2h(float v, __half& hi, __half& lo) {
    hi = __float2half(v);
    lo = __float2half(v - __half2float(hi));
}

// BK=64: A tile 128x72 fp16 (144 B/row), B tile 256x72 fp16
#define A_TILE 18432
#define B_TILE 36864
#define STAGE_BYTES (A_TILE + B_TILE)
#define MMA_SMEM (3 * STAGE_BYTES)

__device__ __forceinline__ void mma_mainloop(
    uint32_t smb, const __half* __restrict__ Ab,
    const __half* __restrict__ Bb, int sA, int sB, int niter,
    int t, int lane, int wm, int wn, float c[4][8][4])
{
    uint32_t aoff[4], boff[4];
    {
        int lr = lane & 15, lc = lane >> 4;
        #pragma unroll
        for (int mi = 0; mi < 4; mi++) aoff[mi] = (wm * 64 + mi * 16 + lr) * 144 + lc * 16;
        #pragma unroll
        for (int nj = 0; nj < 4; nj++) boff[nj] = A_TILE + (wn * 64 + nj * 16 + lr) * 144 + lc * 16;
    }
    int lrow = t >> 3;
    int lc16 = (t & 7) * 16;
    int lcol_el = (t & 7) * 8;

    #pragma unroll
    for (int s = 0; s < 2; s++) {
        uint32_t db = smb + s * STAGE_BYTES;
        #pragma unroll
        for (int i = 0; i < 4; i++) {
            int row = lrow + i * 32;
            cp16(db + row * 144 + lc16, Ab + (size_t)row * sA + s * 64 + lcol_el);
        }
        #pragma unroll
        for (int i = 0; i < 8; i++) {
            int row = lrow + i * 32;
            cp16(db + A_TILE + row * 144 + lc16, Bb + (size_t)row * sB + s * 64 + lcol_el);
        }
        CP_COMMIT();
    }

    for (int ck = 0; ck < niter; ck++) {
        CP_WAIT1();
        __syncthreads();
        int pf = ck + 2;
        if (pf < niter) {
            uint32_t db = smb + (pf % 3) * STAGE_BYTES;
            #pragma unroll
            for (int i = 0; i < 4; i++) {
                int row = lrow + i * 32;
                cp16(db + row * 144 + lc16, Ab + (size_t)row * sA + pf * 64 + lcol_el);
            }
            #pragma unroll
            for (int i = 0; i < 8; i++) {
                int row = lrow + i * 32;
                cp16(db + A_TILE + row * 144 + lc16, Bb + (size_t)row * sB + pf * 64 + lcol_el);
            }
        }
        CP_COMMIT();
        uint32_t sa = smb + (ck % 3) * STAGE_BYTES;
        #pragma unroll
        for (int kk = 0; kk < 4; kk++) {
            uint32_t a[4][4], b[4][4];
            #pragma unroll
            for (int mi = 0; mi < 4; mi++) ldm_x4(a[mi], sa + aoff[mi] + kk * 32);
            #pragma unroll
            for (int nj = 0; nj < 4; nj++) ldm_x4(b[nj], sa + boff[nj] + kk * 32);
            #pragma unroll
            for (int mi = 0; mi < 4; mi++)
                #pragma unroll
                for (int ni = 0; ni < 8; ni++)
                    mma16816(c[mi][ni], a[mi], b[ni >> 1][ni & 1], b[ni >> 1][(ni & 1) + 2]);
        }
    }
}

// ---------------- K1: pool + rmsnorm + gelu -> fp16 [hi,lo] ----------------
__global__ void k_pool(const float* __restrict__ x, const float* __restrict__ w_rms,
                       __half* __restrict__ Xn, __half* __restrict__ Xg) {
    int sp = blockIdx.x;
    const float* xb = x + (size_t)sp * 16 * DIN;
    __shared__ float xp[DIN];
    __shared__ float red[256];
    int t = threadIdx.x;
    float ssq = 0.f;
    for (int c = t; c < DIN; c += 256) {
        float s = 0.f;
        #pragma unroll
        for (int r = 0; r < 16; r++) s += xb[r * DIN + c];
        s *= (1.f / 16.f);
        xp[c] = s;
        ssq += s * s;
    }
    red[t] = ssq;
    __syncthreads();
    for (int o = 128; o > 0; o >>= 1) {
        if (t < o) red[t] += red[t + o];
        __syncthreads();
    }
    float scale = rsqrtf(red[0] / (float)DIN + 1e-6f);
    size_t b = (size_t)sp * KS;
    for (int c = t; c < DIN; c += 256) {
        float v = xp[c] * scale * w_rms[c];
        __half hi, lo;
        split2h(v, hi, lo);
        Xn[b + c] = hi; Xn[b + DIN + c] = lo;
        float g = v * normcdff(v);
        split2h(g, hi, lo);
        Xg[b + c] = hi; Xg[b + DIN + c] = lo;
    }
}

// ---------------- K2: f0 table ----------------
__global__ void k_f0(int* __restrict__ f0) {
    int d = threadIdx.x;
    if (d < SP) {
        const float log_step = (float)(log(481.0) / 32.0);
        int cnt = 0;
        #pragma unroll
        for (int f = 0; f < 32; f++) {
            float cw = (float)f + expf((float)f * log_step);
            if (cw <= (float)d) cnt++;
        }
        f0[d] = cnt;
    }
}

// ---------------- K4: transpose weights -> fp16 [hi,hi] (merged qk + y) ----------------
__global__ void k_wsplit(const float* __restrict__ W_q, const float* __restrict__ W_k,
                         const float* __restrict__ W_yq, const float* __restrict__ W_yk,
                         __half* __restrict__ Ww, __half* __restrict__ Wy) {
    __shared__ float tile[32][33];
    int t = threadIdx.x;
    int bx = blockIdx.x, k0 = blockIdx.y * 32;
    bool isY = bx >= 256;
    int n0 = isY ? (bx - 256) * 32 : bx * 32;
    int Nsrc = isY ? HD : HDTOT;
    const float* srcA = isY ? W_yq : W_q;
    const float* srcB = isY ? W_yk : W_k;
    __half* dst = isY ? Wy : Ww;
    const float* src = (n0 < Nsrc) ? srcA : srcB;
    int nb = (n0 < Nsrc) ? n0 : (n0 - Nsrc);
    #pragma unroll
    for (int i = 0; i < 4; i++) {
        int r = (t >> 5) + i * 8, c = t & 31;
        tile[r][c] = src[(size_t)(k0 + r) * Nsrc + nb + c];
    }
    __syncthreads();
    #pragma unroll
    for (int i = 0; i < 4; i++) {
        int rn = (t >> 5) + i * 8;
        int kk = k0 + (t & 31);
        __half hi = __float2half(tile[t & 31][rn]);
        size_t row = (size_t)(n0 + rn) * KS;
        dst[row + kk] = hi;
        dst[row + DIN + kk] = hi;
    }
}

// ---------------- K5: fused projection GEMM (CTA 128x256) ----------------
__global__ void __launch_bounds__(256) k_proj(
    const __half* __restrict__ Xn, const __half* __restrict__ Xg,
    const __half* __restrict__ Ww, const __half* __restrict__ Wy,
    float* __restrict__ q, float* __restrict__ k,
    float* __restrict__ yq, float* __restrict__ yk)
{
    extern __shared__ char sm[];
    uint32_t smb = smem_u32(sm);
    int t = threadIdx.x, w = t >> 5, lane = t & 31;
    int wm = w >> 2, wn = w & 3;
    int bid = blockIdx.x;
    int mt, nt;
    if (bid < 128) { mt = bid & 3; nt = bid >> 2; }
    else { mt = bid - 128; nt = 32; }

    const __half* Ab = (bid < 128) ? (Xn + (size_t)mt * 128 * KS)
                                   : (Xg + (size_t)mt * 128 * KS);
    const __half* Bb = (nt < 32) ? (Ww + (size_t)nt * 256 * KS) : Wy;

    float c[4][8][4];
    #pragma unroll
    for (int i = 0; i < 4; i++)
        #pragma unroll
        for (int j = 0; j < 8; j++)
            #pragma unroll
            for (int e = 0; e < 4; e++) c[i][j][e] = 0.f;

    mma_mainloop(smb, Ab, Bb, KS, KS, KS / 64, t, lane, wm, wn, c);

    int r0 = lane >> 2, c0 = (lane & 3) * 2;
    int srow0 = mt * 128;
    #pragma unroll
    for (int mi = 0; mi < 4; mi++) {
        #pragma unroll
        for (int ni = 0; ni < 8; ni++) {
            #pragma unroll
            for (int half = 0; half < 2; half++) {
                int s = srow0 + wm * 64 + mi * 16 + r0 + half * 8;
                int colL = wn * 64 + ni * 8 + c0;
                float2 fv = make_float2(c[mi][ni][half * 2], c[mi][ni][half * 2 + 1]);
                if (nt < 32) {
                    int col = nt * 256 + colL;
                    bool isQ = col < HDTOT;
                    float* o = isQ ? q : k;
                    int nn = isQ ? col : col - HDTOT;
                    *(float2*)&o[(size_t)s * HDTOT + nn] = fv;
                } else {
                    float* o = (colL < HD) ? yq : yk;
                    int nn = (colL < HD) ? colL : colL - HD;
                    *(float2*)&o[(size_t)s * HD + nn] = fv;
                }
            }
        }
    }
}

// ---------------- K5s: scores GEMM with inline fp32->fp16 split ----------------
// Per block: m0=128 q rows, n0=256 k rows, head z. K = 256 halves (2-term split).
// A smem: 128 rows x 528 B ([hi x128][lo x128] + pad); B: 256 rows x 528 B ([hi][hi]).
#define SC_ROW 528
#define SC_B_OFF (128 * SC_ROW)
#define SC_SMEM (SC_B_OFF + 256 * SC_ROW)   // 202752
__global__ void __launch_bounds__(256) k_scores(
    const float* __restrict__ q, const float* __restrict__ k,
    float* __restrict__ S)
{
    extern __shared__ char sm[];
    uint32_t smb = smem_u32(sm);
    int t = threadIdx.x, w = t >> 5, lane = t & 31;
    int wm = w >> 2, wn = w & 3;
    int m0 = blockIdx.x * 128, n0 = blockIdx.y * 256, z = blockIdx.z;

    // A = q rows: [hi, lo]
    for (int i = t; i < 4096; i += 256) {
        int r = i >> 5, c4 = (i & 31) * 4;
        float4 v = *(const float4*)&q[(size_t)(m0 + r) * HDTOT + z * HD + c4];
        __half h0, l0, h1, l1, h2, l2, h3, l3;
        split2h(v.x, h0, l0); split2h(v.y, h1, l1);
        split2h(v.z, h2, l2); split2h(v.w, h3, l3);
        __half* row = (__half*)(sm + r * SC_ROW);
        ((__half2*)(row + c4))[0] = __halves2half2(h0, h1);
        ((__half2*)(row + c4))[1] = __halves2half2(h2, h3);
        ((__half2*)(row + 128 + c4))[0] = __halves2half2(l0, l1);
        ((__half2*)(row + 128 + c4))[1] = __halves2half2(l2, l3);
    }
    // B = k rows: [hi, hi]
    for (int i = t; i < 8192; i += 256) {
        int r = i >> 5, c4 = (i & 31) * 4;
        float4 v = *(const float4*)&k[(size_t)(n0 + r) * HDTOT + z * HD + c4];
        __half2 p0 = __halves2half2(__float2half(v.x), __float2half(v.y));
        __half2 p1 = __halves2half2(__float2half(v.z), __float2half(v.w));
        __half* row = (__half*)(sm + SC_B_OFF + r * SC_ROW);
        ((__half2*)(row + c4))[0] = p0;
        ((__half2*)(row + c4))[1] = p1;
        ((__half2*)(row + 128 + c4))[0] = p0;
        ((__half2*)(row + 128 + c4))[1] = p1;
    }
    __syncthreads();

    uint32_t aoff[4], boff[4];
    {
        int lr = lane & 15, lc = lane >> 4;
        #pragma unroll
        for (int mi = 0; mi < 4; mi++) aoff[mi] = smb + (wm * 64 + mi * 16 + lr) * SC_ROW + lc * 16;
        #pragma unroll
        for (int nj = 0; nj < 4; nj++) boff[nj] = smb + SC_B_OFF + (wn * 64 + nj * 16 + lr) * SC_ROW + lc * 16;
    }
    float c[4][8][4];
    #pragma unroll
    for (int i = 0; i < 4; i++)
        #pragma unroll
        for (int j = 0; j < 8; j++)
            #pragma unroll
            for (int e = 0; e < 4; e++) c[i][j][e] = 0.f;

    #pragma unroll
    for (int kk = 0; kk < 16; kk++) {
        uint32_t a[4][4], b[4][4];
        #pragma unroll
        for (int mi = 0; mi < 4; mi++) ldm_x4(a[mi], aoff[mi] + kk * 32);
        #pragma unroll
        for (int nj = 0; nj < 4; nj++) ldm_x4(b[nj], boff[nj] + kk * 32);
        #pragma unroll
        for (int mi = 0; mi < 4; mi++)
            #pragma unroll
            for (int ni = 0; ni < 8; ni++)
                mma16816(c[mi][ni], a[mi], b[ni >> 1][ni & 1], b[ni >> 1][(ni & 1) + 2]);
    }

    int r0 = lane >> 2, c0 = (lane & 3) * 2;
    #pragma unroll
    for (int mi = 0; mi < 4; mi++) {
        #pragma unroll
        for (int ni = 0; ni < 8; ni++) {
            #pragma unroll
            for (int half = 0; half < 2; half++) {
                int row = m0 + wm * 64 + mi * 16 + r0 + half * 8;
                int col = n0 + wn * 64 + ni * 8 + c0;
                float2 fv = make_float2(c[mi][ni][half * 2], c[mi][ni][half * 2 + 1]);
                *(float2*)&S[((size_t)(z * SP + row)) * SP + col] = fv;
            }
        }
    }
}

// ---------------- K6: suffix tables (merged TQ/TK via z) ----------------
__global__ void __launch_bounds__(256) k_suffix(const float* __restrict__ qk0,
                                                const float* __restrict__ qk1,
                                                const float* __restrict__ rb0,
                                                const float* __restrict__ rb1,
                                                const float* __restrict__ W_pos,
                                                const float* __restrict__ b_pos,
                                                float* __restrict__ T0,
                                                float* __restrict__ T1) {
    extern __shared__ float smf[];
    float* ws = smf;
    float* qs = ws + 65 * 132;
    float* Ms = qs + 32 * 132;
    int sel = blockIdx.z;
    const float* qk    = sel ? qk1 : qk0;
    const float* rbias = sel ? rb1 : rb0;
    float* T           = sel ? T1 : T0;
    int h = blockIdx.y;
    int q0 = blockIdx.x * 32;
    int t = threadIdx.x;
    for (int i = t; i < 65 * 128; i += 256) {
        int f = i >> 7, c = i & 127;
        ws[f * 132 + c] = (f < 64) ? W_pos[f * HDTOT + h * HD + c] : b_pos[h * HD + c];
    }
    for (int i = t; i < 32 * 128; i += 256) {
        int r = i >> 7, c = i & 127;
        qs[r * 132 + c] = qk[(size_t)(q0 + r) * HDTOT + h * HD + c] + rbias[h * HD + c];
    }
    __syncthreads();
    for (int i = t; i < 32 * 65; i += 256) {
        int r = i / 65, f = i % 65;
        const float4* qr = (const float4*)&qs[r * 132];
        const float4* wr = (const float4*)&ws[f * 132];
        float acc = 0.f;
        #pragma unroll
        for (int c4 = 0; c4 < 32; c4++) {
            float4 a = qr[c4], b = wr[c4];
            acc += a.x * b.x + a.y * b.y + a.z * b.z + a.w * b.w;
        }
        Ms[r * 65 + f] = acc;
    }
    __syncthreads();
    for (int i = t; i < 32 * 33; i += 256) {
        int r = i / 33, j = i % 33;
        float sa = Ms[r * 65 + 64];
        float sb = 0.f;
        for (int f = j; f < 32; f++) { sa += Ms[r * 65 + f]; sb += Ms[r * 65 + 32 + f]; }
        int q = q0 + r;
        T[((j * SP + q) * NH + h) * 2] = sa;
        T[((j * SP + q) * NH + h) * 2 + 1] = sb;
    }
}

// ---------------- K7: fold suffix tables through W_pair ----------------
__global__ void __launch_bounds__(128) k_fold(const float* __restrict__ TQ,
                                              const float* __restrict__ TK,
                                              const float* __restrict__ Wp,
                                              float* __restrict__ RQ,
                                              float* __restrict__ RK) {
    __shared__ float tq[33 * 64], tk[33 * 64];
    int q = blockIdx.x, t = threadIdx.x;
    for (int i = t; i < 33 * 64; i += 128) {
        int j = i >> 6, r = i & 63;
        tq[i] = TQ[((size_t)j * SP + q) * 64 + r];
        tk[i] = TK[((size_t)j * SP + q) * 64 + r];
    }
    float wcol[NH];
    #pragma unroll
    for (int h = 0; h < NH; h++) wcol[h] = Wp[h * HD + t];
    __syncthreads();
    for (int j = 0; j < 33; j++) {
        float aa = 0.f, ab = 0.f, ba = 0.f, bb = 0.f;
        const float* tqj = &tq[j * 64];
        const float* tkj = &tk[j * 64];
        #pragma unroll
        for (int h = 0; h < NH; h++) {
            float w = wcol[h];
            aa += tqj[2 * h] * w;  ab += tqj[2 * h + 1] * w;
            ba += tkj[2 * h] * w;  bb += tkj[2 * h + 1] * w;
        }
        size_t ob = ((size_t)j * SP + q) * 256 + t * 2;
        RQ[ob] = aa; RQ[ob + 1] = ab;
        RK[ob] = ba; RK[ob + 1] = bb;
    }
}

// ---------------- K8: final pass (FFMA2 packed fp32x2) ----------------
__global__ void __launch_bounds__(256) k_pair2(const float* __restrict__ S,
                                               const float* __restrict__ RQ,
                                               const float* __restrict__ RK,
                                               const int* __restrict__ f0tab,
                                               const float* __restrict__ Wp,
                                               const float* __restrict__ bp,
                                               const float* __restrict__ yq,
                                               const float* __restrict__ yk,
                                               float* __restrict__ out) {
    __shared__ __align__(16) float Sh[128 * 36];
    int t = threadIdx.x;
    int q = blockIdx.x, k0 = blockIdx.y * 128;
    for (int i = t; i < 4096; i += 256) {
        int h = i >> 7, kk = i & 127;
        Sh[kk * 36 + h] = S[(((size_t)h * SP + q) << 9) + k0 + kk];
    }
    int d = t & 127, g = t >> 7;
    uint64_t w2[16];
    #pragma unroll
    for (int h2 = 0; h2 < 16; h2++) {
        float w0 = Wp[(2 * h2) * HD + d], w1 = Wp[(2 * h2 + 1) * HD + d];
        asm("mov.b64 %0, {%1,%2};" : "=l"(w2[h2]) : "f"(w0), "f"(w1));
    }
    float base0 = bp[d] + yq[q * HD + d];
    __syncthreads();
    for (int kk = g * 64; kk < g * 64 + 64; kk++) {
        int k = k0 + kk;
        int delta = k - q;
        int dd = delta >= 0 ? delta : -delta;
        float sgn = delta > 0 ? 1.f : (delta < 0 ? -1.f : 0.f);
        int j = f0tab[dd];
        float2 rq = *(const float2*)&RQ[((size_t)j * SP + q) * 256 + d * 2];
        float2 rk = *(const float2*)&RK[((size_t)j * SP + k) * 256 + d * 2];
        float base = base0 + yk[k * HD + d]
                   + 0.5f * (rq.x + rk.x) + 0.5f * sgn * (rq.y - rk.y);
        const ulonglong2* sr2 = (const ulonglong2*)&Sh[kk * 36];
        uint64_t acc2 = 0;
        #pragma unroll
        for (int h8 = 0; h8 < 8; h8++) {
            ulonglong2 v = sr2[h8];
            asm("fma.rn.f32x2 %0, %1, %2, %0;" : "+l"(acc2) : "l"(v.x), "l"(w2[h8 * 2]));
            asm("fma.rn.f32x2 %0, %1, %2, %0;" : "+l"(acc2) : "l"(v.y), "l"(w2[h8 * 2 + 1]));
        }
        float lo, hi;
        asm("mov.b64 {%0,%1}, %2;" : "=f"(lo), "=f"(hi) : "l"(acc2));
        out[((size_t)(q * SP + k)) * HD + d] = base + lo + hi;
    }
}

// ---------------- launcher ----------------
#define SUF_SMEM ((65 * 132 + 32 * 132 + 32 * 65) * 4)

extern "C" void kernel_launch(void* const* d_in, const int* in_sizes, int n_in,
                              void* d_out, int out_size) {
    const float* x      = (const float*)d_in[0];
    const float* w_rms  = (const float*)d_in[1];
    const float* W_q    = (const float*)d_in[2];
    const float* W_k    = (const float*)d_in[3];
    const float* W_pos  = (const float*)d_in[4];
    const float* b_pos  = (const float*)d_in[5];
    const float* qrb    = (const float*)d_in[6];
    const float* krb    = (const float*)d_in[7];
    const float* W_yq   = (const float*)d_in[8];
    const float* W_yk   = (const float*)d_in[9];
    const float* W_pair = (const float*)d_in[10];
    const float* b_pair = (const float*)d_in[11];
    float* out = (float*)d_out;

    float *qb, *kb, *yq, *yk, *TQ, *TK, *RQ, *RK, *Sb;
    __half *Xn, *Xg, *Ww, *Wy;
    int* f0;
    cudaGetSymbolAddress((void**)&qb, g_q);
    cudaGetSymbolAddress((void**)&kb, g_k);
    cudaGetSymbolAddress((void**)&yq, g_yq);
    cudaGetSymbolAddress((void**)&yk, g_yk);
    cudaGetSymbolAddress((void**)&TQ, g_TQ);
    cudaGetSymbolAddress((void**)&TK, g_TK);
    cudaGetSymbolAddress((void**)&RQ, g_RQ);
    cudaGetSymbolAddress((void**)&RK, g_RK);
    cudaGetSymbolAddress((void**)&Sb, g_S);
    cudaGetSymbolAddress((void**)&Xn, g_Xn);
    cudaGetSymbolAddress((void**)&Xg, g_Xg);
    cudaGetSymbolAddress((void**)&Ww, g_Ww);
    cudaGetSymbolAddress((void**)&Wy, g_Wy);
    cudaGetSymbolAddress((void**)&f0, g_f0);

    cudaFuncSetAttribute(k_proj, cudaFuncAttributeMaxDynamicSharedMemorySize, MMA_SMEM);
    cudaFuncSetAttribute(k_scores, cudaFuncAttributeMaxDynamicSharedMemorySize, SC_SMEM);
    cudaFuncSetAttribute(k_suffix, cudaFuncAttributeMaxDynamicSharedMemorySize, SUF_SMEM);

    cudaStream_t s1;
    cudaStreamCreateWithFlags(&s1, cudaStreamNonBlocking);
    cudaEvent_t e2, e3;
    cudaEventCreateWithFlags(&e2, cudaEventDisableTiming);
    cudaEventCreateWithFlags(&e3, cudaEventDisableTiming);

    // default stream: critical path; launch idx 3 (profiled) = k_scores
    k_wsplit<<<dim3(264, DIN / 32), 256>>>(W_q, W_k, W_yq, W_yk, Ww, Wy);   // 1
    k_pool<<<SP, 256>>>(x, w_rms, Xn, Xg);                                  // 2
    k_proj<<<132, 256, MMA_SMEM>>>(Xn, Xg, Ww, Wy, qb, kb, yq, yk);         // 3
    cudaEventRecord(e2, 0);
    k_scores<<<dim3(4, 2, NH), 256, SC_SMEM>>>(qb, kb, Sb);                 // 4 (profiled)

    // side stream: f0 + suffix + fold
    k_f0<<<1, 512, 0, s1>>>(f0);
    cudaStreamWaitEvent(s1, e2, 0);
    dim3 gs(SP / 32, NH, 2);
    k_suffix<<<gs, 256, SUF_SMEM, s1>>>(qb, kb, qrb, krb, W_pos, b_pos, TQ, TK);
    k_fold<<<SP, 128, 0, s1>>>(TQ, TK, W_pair, RQ, RK);
    cudaEventRecord(e3, s1);

    // join -> pair2
    cudaStreamWaitEvent(0, e3, 0);
    k_pair2<<<dim3(SP, 4), 256>>>(Sb, RQ, RK, f0, W_pair, b_pair, yq, yk, out);

    cudaEventDestroy(e2);
    cudaEventDestroy(e3);
    cudaStreamDestroy(s1);
}

// round 15
// speedup vs baseline: 1.1679x; 1.0209x over previous
#include <cuda_runtime.h>
#include <cuda_fp16.h>
#include <math.h>
#include <stdint.h>

#define SP    512
#define DIN   1536
#define NH    32
#define HD    128
#define HDTOT 4096
#define KS    3072   // 2*DIN  (fp16 2-term split)

// ---------------- scratch ----------------
__device__ __half g_Xn[SP*KS];
__device__ __half g_Xg[SP*KS];
__device__ __half g_Ww[(size_t)2*HDTOT*KS];
__device__ __half g_Wy[2*HD*KS];
__device__ float g_q[SP*HDTOT];
__device__ float g_k[SP*HDTOT];
__device__ float g_yq[SP*HD];
__device__ float g_yk[SP*HD];
__device__ float g_S[(size_t)NH*SP*SP];
__device__ float g_TQ[33*SP*NH*2];
__device__ float g_TK[33*SP*NH*2];
__device__ float g_RQ[33*SP*HD*2];
__device__ float g_RK[33*SP*HD*2];
__device__ int   g_f0[SP];

// ---------------- helpers ----------------
__device__ __forceinline__ uint32_t smem_u32(const void* p) {
    uint32_t a;
    asm("{ .reg .u64 t; cvta.to.shared.u64 t, %1; cvt.u32.u64 %0, t; }" : "=r"(a) : "l"(p));
    return a;
}
__device__ __forceinline__ void cp16(uint32_t dst, const void* src) {
    asm volatile("cp.async.cg.shared.global [%0], [%1], 16;" :: "r"(dst), "l"(src));
}
#define CP_COMMIT() asm volatile("cp.async.commit_group;" ::: "memory")
#define CP_WAIT1()  asm volatile("cp.async.wait_group 1;" ::: "memory")

__device__ __forceinline__ void ldm_x4(uint32_t* r, uint32_t addr) {
    asm volatile("ldmatrix.sync.aligned.m8n8.x4.shared.b16 {%0,%1,%2,%3}, [%4];"
                 : "=r"(r[0]), "=r"(r[1]), "=r"(r[2]), "=r"(r[3]) : "r"(addr));
}
__device__ __forceinline__ void mma16816(float* c, const uint32_t* a, uint32_t b0, uint32_t b1) {
    asm volatile("mma.sync.aligned.m16n8k16.row.col.f32.f16.f16.f32 "
                 "{%0,%1,%2,%3}, {%4,%5,%6,%7}, {%8,%9}, {%0,%1,%2,%3};"
                 : "+f"(c[0]), "+f"(c[1]), "+f"(c[2]), "+f"(c[3])
                 : "r"(a[0]), "r"(a[1]), "r"(a[2]), "r"(a[3]), "r"(b0), "r"(b1));
}
__device__ __forceinline__ void split2h(float v, __half& hi, __half& lo) {
    hi = __float2half(v);
    lo = __float2half(v - __half2float(hi));
}

// BK=64: A tile 128x72 fp16 (144 B/row), B tile 256x72 fp16
#define A_TILE 18432
#define B_TILE 36864
#define STAGE_BYTES (A_TILE + B_TILE)
#define MMA_SMEM (3 * STAGE_BYTES)

__device__ __forceinline__ void mma_mainloop(
    uint32_t smb, const __half* __restrict__ Ab,
    const __half* __restrict__ Bb, int sA, int sB, int niter,
    int t, int lane, int wm, int wn, float c[4][8][4])
{
    uint32_t aoff[4], boff[4];
    {
        int lr = lane & 15, lc = lane >> 4;
        #pragma unroll
        for (int mi = 0; mi < 4; mi++) aoff[mi] = (wm * 64 + mi * 16 + lr) * 144 + lc * 16;
        #pragma unroll
        for (int nj = 0; nj < 4; nj++) boff[nj] = A_TILE + (wn * 64 + nj * 16 + lr) * 144 + lc * 16;
    }
    int lrow = t >> 3;
    int lc16 = (t & 7) * 16;
    int lcol_el = (t & 7) * 8;

    #pragma unroll
    for (int s = 0; s < 2; s++) {
        uint32_t db = smb + s * STAGE_BYTES;
        #pragma unroll
        for (int i = 0; i < 4; i++) {
            int row = lrow + i * 32;
            cp16(db + row * 144 + lc16, Ab + (size_t)row * sA + s * 64 + lcol_el);
        }
        #pragma unroll
        for (int i = 0; i < 8; i++) {
            int row = lrow + i * 32;
            cp16(db + A_TILE + row * 144 + lc16, Bb + (size_t)row * sB + s * 64 + lcol_el);
        }
        CP_COMMIT();
    }

    for (int ck = 0; ck < niter; ck++) {
        CP_WAIT1();
        __syncthreads();
        int pf = ck + 2;
        if (pf < niter) {
            uint32_t db = smb + (pf % 3) * STAGE_BYTES;
            #pragma unroll
            for (int i = 0; i < 4; i++) {
                int row = lrow + i * 32;
                cp16(db + row * 144 + lc16, Ab + (size_t)row * sA + pf * 64 + lcol_el);
            }
            #pragma unroll
            for (int i = 0; i < 8; i++) {
                int row = lrow + i * 32;
                cp16(db + A_TILE + row * 144 + lc16, Bb + (size_t)row * sB + pf * 64 + lcol_el);
            }
        }
        CP_COMMIT();
        uint32_t sa = smb + (ck % 3) * STAGE_BYTES;
        #pragma unroll
        for (int kk = 0; kk < 4; kk++) {
            uint32_t a[4][4], b[4][4];
            #pragma unroll
            for (int mi = 0; mi < 4; mi++) ldm_x4(a[mi], sa + aoff[mi] + kk * 32);
            #pragma unroll
            for (int nj = 0; nj < 4; nj++) ldm_x4(b[nj], sa + boff[nj] + kk * 32);
            #pragma unroll
            for (int mi = 0; mi < 4; mi++)
                #pragma unroll
                for (int ni = 0; ni < 8; ni++)
                    mma16816(c[mi][ni], a[mi], b[ni >> 1][ni & 1], b[ni >> 1][(ni & 1) + 2]);
        }
    }
}

// ---------------- K1: pool + rmsnorm + gelu -> fp16 [hi,lo] ----------------
__global__ void k_pool(const float* __restrict__ x, const float* __restrict__ w_rms,
                       __half* __restrict__ Xn, __half* __restrict__ Xg) {
    int sp = blockIdx.x;
    const float* xb = x + (size_t)sp * 16 * DIN;
    __shared__ float xp[DIN];
    __shared__ float red[256];
    int t = threadIdx.x;
    float ssq = 0.f;
    for (int c = t; c < DIN; c += 256) {
        float s = 0.f;
        #pragma unroll
        for (int r = 0; r < 16; r++) s += xb[r * DIN + c];
        s *= (1.f / 16.f);
        xp[c] = s;
        ssq += s * s;
    }
    red[t] = ssq;
    __syncthreads();
    for (int o = 128; o > 0; o >>= 1) {
        if (t < o) red[t] += red[t + o];
        __syncthreads();
    }
    float scale = rsqrtf(red[0] / (float)DIN + 1e-6f);
    size_t b = (size_t)sp * KS;
    for (int c = t; c < DIN; c += 256) {
        float v = xp[c] * scale * w_rms[c];
        __half hi, lo;
        split2h(v, hi, lo);
        Xn[b + c] = hi; Xn[b + DIN + c] = lo;
        float g = v * normcdff(v);
        split2h(g, hi, lo);
        Xg[b + c] = hi; Xg[b + DIN + c] = lo;
    }
}

// ---------------- K2: f0 table ----------------
__global__ void k_f0(int* __restrict__ f0) {
    int d = threadIdx.x;
    if (d < SP) {
        const float log_step = (float)(log(481.0) / 32.0);
        int cnt = 0;
        #pragma unroll
        for (int f = 0; f < 32; f++) {
            float cw = (float)f + expf((float)f * log_step);
            if (cw <= (float)d) cnt++;
        }
        f0[d] = cnt;
    }
}

// ---------------- K4: transpose weights -> fp16 [hi,hi] (merged qk + y) ----------------
__global__ void k_wsplit(const float* __restrict__ W_q, const float* __restrict__ W_k,
                         const float* __restrict__ W_yq, const float* __restrict__ W_yk,
                         __half* __restrict__ Ww, __half* __restrict__ Wy) {
    __shared__ float tile[32][33];
    int t = threadIdx.x;
    int bx = blockIdx.x, k0 = blockIdx.y * 32;
    bool isY = bx >= 256;
    int n0 = isY ? (bx - 256) * 32 : bx * 32;
    int Nsrc = isY ? HD : HDTOT;
    const float* srcA = isY ? W_yq : W_q;
    const float* srcB = isY ? W_yk : W_k;
    __half* dst = isY ? Wy : Ww;
    const float* src = (n0 < Nsrc) ? srcA : srcB;
    int nb = (n0 < Nsrc) ? n0 : (n0 - Nsrc);
    #pragma unroll
    for (int i = 0; i < 4; i++) {
        int r = (t >> 5) + i * 8, c = t & 31;
        tile[r][c] = src[(size_t)(k0 + r) * Nsrc + nb + c];
    }
    __syncthreads();
    #pragma unroll
    for (int i = 0; i < 4; i++) {
        int rn = (t >> 5) + i * 8;
        int kk = k0 + (t & 31);
        __half hi = __float2half(tile[t & 31][rn]);
        size_t row = (size_t)(n0 + rn) * KS;
        dst[row + kk] = hi;
        dst[row + DIN + kk] = hi;
    }
}

// ---------------- K5: fused projection GEMM (CTA 128x256) ----------------
__global__ void __launch_bounds__(256) k_proj(
    const __half* __restrict__ Xn, const __half* __restrict__ Xg,
    const __half* __restrict__ Ww, const __half* __restrict__ Wy,
    float* __restrict__ q, float* __restrict__ k,
    float* __restrict__ yq, float* __restrict__ yk)
{
    extern __shared__ char sm[];
    uint32_t smb = smem_u32(sm);
    int t = threadIdx.x, w = t >> 5, lane = t & 31;
    int wm = w >> 2, wn = w & 3;
    int bid = blockIdx.x;
    int mt, nt;
    if (bid < 128) { mt = bid & 3; nt = bid >> 2; }
    else { mt = bid - 128; nt = 32; }

    const __half* Ab = (bid < 128) ? (Xn + (size_t)mt * 128 * KS)
                                   : (Xg + (size_t)mt * 128 * KS);
    const __half* Bb = (nt < 32) ? (Ww + (size_t)nt * 256 * KS) : Wy;

    float c[4][8][4];
    #pragma unroll
    for (int i = 0; i < 4; i++)
        #pragma unroll
        for (int j = 0; j < 8; j++)
            #pragma unroll
            for (int e = 0; e < 4; e++) c[i][j][e] = 0.f;

    mma_mainloop(smb, Ab, Bb, KS, KS, KS / 64, t, lane, wm, wn, c);

    int r0 = lane >> 2, c0 = (lane & 3) * 2;
    int srow0 = mt * 128;
    #pragma unroll
    for (int mi = 0; mi < 4; mi++) {
        #pragma unroll
        for (int ni = 0; ni < 8; ni++) {
            #pragma unroll
            for (int half = 0; half < 2; half++) {
                int s = srow0 + wm * 64 + mi * 16 + r0 + half * 8;
                int colL = wn * 64 + ni * 8 + c0;
                float2 fv = make_float2(c[mi][ni][half * 2], c[mi][ni][half * 2 + 1]);
                if (nt < 32) {
                    int col = nt * 256 + colL;
                    bool isQ = col < HDTOT;
                    float* o = isQ ? q : k;
                    int nn = isQ ? col : col - HDTOT;
                    *(float2*)&o[(size_t)s * HDTOT + nn] = fv;
                } else {
                    float* o = (colL < HD) ? yq : yk;
                    int nn = (colL < HD) ? colL : colL - HD;
                    *(float2*)&o[(size_t)s * HD + nn] = fv;
                }
            }
        }
    }
}

// ---------------- K5s: scores GEMM, 128x128 tile, 2 CTAs/SM ----------------
// A = q rows, K=256 halves [hi(0..127) | lo(128..255)]; B = k rows, K=128 [hi].
// kk 0..7 uses A-hi x B-hi; kk 8..15 uses A-lo x B-hi (same B columns).
#define SC_AROW 528                        // 256 halves + 8 pad
#define SC_BROW 272                        // 128 halves + 8 pad
#define SC_B_OFF (128 * SC_AROW)           // 67584
#define SC_SMEM (SC_B_OFF + 128 * SC_BROW) // 102400
__global__ void __launch_bounds__(256, 2) k_scores(
    const float* __restrict__ q, const float* __restrict__ k,
    float* __restrict__ S)
{
    extern __shared__ char sm[];
    uint32_t smb = smem_u32(sm);
    int t = threadIdx.x, w = t >> 5, lane = t & 31;
    int wm = w >> 2, wn = w & 3;
    int m0 = blockIdx.x * 128, n0 = blockIdx.y * 128, z = blockIdx.z;

    // A = q rows: [hi | lo]
    for (int i = t; i < 4096; i += 256) {
        int r = i >> 5, c4 = (i & 31) * 4;
        float4 v = *(const float4*)&q[(size_t)(m0 + r) * HDTOT + z * HD + c4];
        __half h0, l0, h1, l1, h2, l2, h3, l3;
        split2h(v.x, h0, l0); split2h(v.y, h1, l1);
        split2h(v.z, h2, l2); split2h(v.w, h3, l3);
        __half* row = (__half*)(sm + r * SC_AROW);
        ((__half2*)(row + c4))[0] = __halves2half2(h0, h1);
        ((__half2*)(row + c4))[1] = __halves2half2(h2, h3);
        ((__half2*)(row + 128 + c4))[0] = __halves2half2(l0, l1);
        ((__half2*)(row + 128 + c4))[1] = __halves2half2(l2, l3);
    }
    // B = k rows: [hi]
    for (int i = t; i < 4096; i += 256) {
        int r = i >> 5, c4 = (i & 31) * 4;
        float4 v = *(const float4*)&k[(size_t)(n0 + r) * HDTOT + z * HD + c4];
        __half* row = (__half*)(sm + SC_B_OFF + r * SC_BROW);
        ((__half2*)(row + c4))[0] = __halves2half2(__float2half(v.x), __float2half(v.y));
        ((__half2*)(row + c4))[1] = __halves2half2(__float2half(v.z), __float2half(v.w));
    }
    __syncthreads();

    uint32_t aoff[4], boff[2];
    {
        int lr = lane & 15, lc = lane >> 4;
        #pragma unroll
        for (int mi = 0; mi < 4; mi++) aoff[mi] = smb + (wm * 64 + mi * 16 + lr) * SC_AROW + lc * 16;
        #pragma unroll
        for (int nj = 0; nj < 2; nj++) boff[nj] = smb + SC_B_OFF + (wn * 32 + nj * 16 + lr) * SC_BROW + lc * 16;
    }
    float c[4][4][4];
    #pragma unroll
    for (int i = 0; i < 4; i++)
        #pragma unroll
        for (int j = 0; j < 4; j++)
            #pragma unroll
            for (int e = 0; e < 4; e++) c[i][j][e] = 0.f;

    #pragma unroll
    for (int kk = 0; kk < 16; kk++) {
        uint32_t a[4][4], b[2][4];
        #pragma unroll
        for (int mi = 0; mi < 4; mi++) ldm_x4(a[mi], aoff[mi] + kk * 32);
        #pragma unroll
        for (int nj = 0; nj < 2; nj++) ldm_x4(b[nj], boff[nj] + (kk & 7) * 32);
        #pragma unroll
        for (int mi = 0; mi < 4; mi++)
            #pragma unroll
            for (int ni = 0; ni < 4; ni++)
                mma16816(c[mi][ni], a[mi], b[ni >> 1][ni & 1], b[ni >> 1][(ni & 1) + 2]);
    }

    int r0 = lane >> 2, c0 = (lane & 3) * 2;
    #pragma unroll
    for (int mi = 0; mi < 4; mi++) {
        #pragma unroll
        for (int ni = 0; ni < 4; ni++) {
            #pragma unroll
            for (int half = 0; half < 2; half++) {
                int row = m0 + wm * 64 + mi * 16 + r0 + half * 8;
                int col = n0 + wn * 32 + ni * 8 + c0;
                float2 fv = make_float2(c[mi][ni][half * 2], c[mi][ni][half * 2 + 1]);
                *(float2*)&S[((size_t)(z * SP + row)) * SP + col] = fv;
            }
        }
    }
}

// ---------------- K6: suffix tables (merged TQ/TK via z) ----------------
__global__ void __launch_bounds__(256) k_suffix(const float* __restrict__ qk0,
                                                const float* __restrict__ qk1,
                                                const float* __restrict__ rb0,
                                                const float* __restrict__ rb1,
                                                const float* __restrict__ W_pos,
                                                const float* __restrict__ b_pos,
                                                float* __restrict__ T0,
                                                float* __restrict__ T1) {
    extern __shared__ float smf[];
    float* ws = smf;
    float* qs = ws + 65 * 132;
    float* Ms = qs + 32 * 132;
    int sel = blockIdx.z;
    const float* qk    = sel ? qk1 : qk0;
    const float* rbias = sel ? rb1 : rb0;
    float* T           = sel ? T1 : T0;
    int h = blockIdx.y;
    int q0 = blockIdx.x * 32;
    int t = threadIdx.x;
    for (int i = t; i < 65 * 128; i += 256) {
        int f = i >> 7, c = i & 127;
        ws[f * 132 + c] = (f < 64) ? W_pos[f * HDTOT + h * HD + c] : b_pos[h * HD + c];
    }
    for (int i = t; i < 32 * 128; i += 256) {
        int r = i >> 7, c = i & 127;
        qs[r * 132 + c] = qk[(size_t)(q0 + r) * HDTOT + h * HD + c] + rbias[h * HD + c];
    }
    __syncthreads();
    for (int i = t; i < 32 * 65; i += 256) {
        int r = i / 65, f = i % 65;
        const float4* qr = (const float4*)&qs[r * 132];
        const float4* wr = (const float4*)&ws[f * 132];
        float acc = 0.f;
        #pragma unroll
        for (int c4 = 0; c4 < 32; c4++) {
            float4 a = qr[c4], b = wr[c4];
            acc += a.x * b.x + a.y * b.y + a.z * b.z + a.w * b.w;
        }
        Ms[r * 65 + f] = acc;
    }
    __syncthreads();
    for (int i = t; i < 32 * 33; i += 256) {
        int r = i / 33, j = i % 33;
        float sa = Ms[r * 65 + 64];
        float sb = 0.f;
        for (int f = j; f < 32; f++) { sa += Ms[r * 65 + f]; sb += Ms[r * 65 + 32 + f]; }
        int q = q0 + r;
        T[((j * SP + q) * NH + h) * 2] = sa;
        T[((j * SP + q) * NH + h) * 2 + 1] = sb;
    }
}

// ---------------- K7: fold suffix tables through W_pair ----------------
__global__ void __launch_bounds__(128) k_fold(const float* __restrict__ TQ,
                                              const float* __restrict__ TK,
                                              const float* __restrict__ Wp,
                                              float* __restrict__ RQ,
                                              float* __restrict__ RK) {
    __shared__ float tq[33 * 64], tk[33 * 64];
    int q = blockIdx.x, t = threadIdx.x;
    for (int i = t; i < 33 * 64; i += 128) {
        int j = i >> 6, r = i & 63;
        tq[i] = TQ[((size_t)j * SP + q) * 64 + r];
        tk[i] = TK[((size_t)j * SP + q) * 64 + r];
    }
    float wcol[NH];
    #pragma unroll
    for (int h = 0; h < NH; h++) wcol[h] = Wp[h * HD + t];
    __syncthreads();
    for (int j = 0; j < 33; j++) {
        float aa = 0.f, ab = 0.f, ba = 0.f, bb = 0.f;
        const float* tqj = &tq[j * 64];
        const float* tkj = &tk[j * 64];
        #pragma unroll
        for (int h = 0; h < NH; h++) {
            float w = wcol[h];
            aa += tqj[2 * h] * w;  ab += tqj[2 * h + 1] * w;
            ba += tkj[2 * h] * w;  bb += tkj[2 * h + 1] * w;
        }
        size_t ob = ((size_t)j * SP + q) * 256 + t * 2;
        RQ[ob] = aa; RQ[ob + 1] = ab;
        RK[ob] = ba; RK[ob + 1] = bb;
    }
}

// ---------------- K8: final pass (FFMA2 packed fp32x2) ----------------
__global__ void __launch_bounds__(256) k_pair2(const float* __restrict__ S,
                                               const float* __restrict__ RQ,
                                               const float* __restrict__ RK,
                                               const int* __restrict__ f0tab,
                                               const float* __restrict__ Wp,
                                               const float* __restrict__ bp,
                                               const float* __restrict__ yq,
                                               const float* __restrict__ yk,
                                               float* __restrict__ out) {
    __shared__ __align__(16) float Sh[128 * 36];
    int t = threadIdx.x;
    int q = blockIdx.x, k0 = blockIdx.y * 128;
    for (int i = t; i < 4096; i += 256) {
        int h = i >> 7, kk = i & 127;
        Sh[kk * 36 + h] = S[(((size_t)h * SP + q) << 9) + k0 + kk];
    }
    int d = t & 127, g = t >> 7;
    uint64_t w2[16];
    #pragma unroll
    for (int h2 = 0; h2 < 16; h2++) {
        float w0 = Wp[(2 * h2) * HD + d], w1 = Wp[(2 * h2 + 1) * HD + d];
        asm("mov.b64 %0, {%1,%2};" : "=l"(w2[h2]) : "f"(w0), "f"(w1));
    }
    float base0 = bp[d] + yq[q * HD + d];
    __syncthreads();
    for (int kk = g * 64; kk < g * 64 + 64; kk++) {
        int k = k0 + kk;
        int delta = k - q;
        int dd = delta >= 0 ? delta : -delta;
        float sgn = delta > 0 ? 1.f : (delta < 0 ? -1.f : 0.f);
        int j = f0tab[dd];
        float2 rq = *(const float2*)&RQ[((size_t)j * SP + q) * 256 + d * 2];
        float2 rk = *(const float2*)&RK[((size_t)j * SP + k) * 256 + d * 2];
        float base = base0 + yk[k * HD + d]
                   + 0.5f * (rq.x + rk.x) + 0.5f * sgn * (rq.y - rk.y);
        const ulonglong2* sr2 = (const ulonglong2*)&Sh[kk * 36];
        uint64_t acc2 = 0;
        #pragma unroll
        for (int h8 = 0; h8 < 8; h8++) {
            ulonglong2 v = sr2[h8];
            asm("fma.rn.f32x2 %0, %1, %2, %0;" : "+l"(acc2) : "l"(v.x), "l"(w2[h8 * 2]));
            asm("fma.rn.f32x2 %0, %1, %2, %0;" : "+l"(acc2) : "l"(v.y), "l"(w2[h8 * 2 + 1]));
        }
        float lo, hi;
        asm("mov.b64 {%0,%1}, %2;" : "=f"(lo), "=f"(hi) : "l"(acc2));
        out[((size_t)(q * SP + k)) * HD + d] = base + lo + hi;
    }
}

// ---------------- launcher ----------------
#define SUF_SMEM ((65 * 132 + 32 * 132 + 32 * 65) * 4)

extern "C" void kernel_launch(void* const* d_in, const int* in_sizes, int n_in,
                              void* d_out, int out_size) {
    const float* x      = (const float*)d_in[0];
    const float* w_rms  = (const float*)d_in[1];
    const float* W_q    = (const float*)d_in[2];
    const float* W_k    = (const float*)d_in[3];
    const float* W_pos  = (const float*)d_in[4];
    const float* b_pos  = (const float*)d_in[5];
    const float* qrb    = (const float*)d_in[6];
    const float* krb    = (const float*)d_in[7];
    const float* W_yq   = (const float*)d_in[8];
    const float* W_yk   = (const float*)d_in[9];
    const float* W_pair = (const float*)d_in[10];
    const float* b_pair = (const float*)d_in[11];
    float* out = (float*)d_out;

    float *qb, *kb, *yq, *yk, *TQ, *TK, *RQ, *RK, *Sb;
    __half *Xn, *Xg, *Ww, *Wy;
    int* f0;
    cudaGetSymbolAddress((void**)&qb, g_q);
    cudaGetSymbolAddress((void**)&kb, g_k);
    cudaGetSymbolAddress((void**)&yq, g_yq);
    cudaGetSymbolAddress((void**)&yk, g_yk);
    cudaGetSymbolAddress((void**)&TQ, g_TQ);
    cudaGetSymbolAddress((void**)&TK, g_TK);
    cudaGetSymbolAddress((void**)&RQ, g_RQ);
    cudaGetSymbolAddress((void**)&RK, g_RK);
    cudaGetSymbolAddress((void**)&Sb, g_S);
    cudaGetSymbolAddress((void**)&Xn, g_Xn);
    cudaGetSymbolAddress((void**)&Xg, g_Xg);
    cudaGetSymbolAddress((void**)&Ww, g_Ww);
    cudaGetSymbolAddress((void**)&Wy, g_Wy);
    cudaGetSymbolAddress((void**)&f0, g_f0);

    cudaFuncSetAttribute(k_proj, cudaFuncAttributeMaxDynamicSharedMemorySize, MMA_SMEM);
    cudaFuncSetAttribute(k_scores, cudaFuncAttributeMaxDynamicSharedMemorySize, SC_SMEM);
    cudaFuncSetAttribute(k_suffix, cudaFuncAttributeMaxDynamicSharedMemorySize, SUF_SMEM);

    cudaStream_t s1;
    cudaStreamCreateWithFlags(&s1, cudaStreamNonBlocking);
    cudaEvent_t e2, e3;
    cudaEventCreateWithFlags(&e2, cudaEventDisableTiming);
    cudaEventCreateWithFlags(&e3, cudaEventDisableTiming);

    // default stream: critical path; launch idx 4 (profiled) = k_scores
    k_wsplit<<<dim3(264, DIN / 32), 256>>>(W_q, W_k, W_yq, W_yk, Ww, Wy);   // 1
    k_pool<<<SP, 256>>>(x, w_rms, Xn, Xg);                                  // 2
    k_proj<<<132, 256, MMA_SMEM>>>(Xn, Xg, Ww, Wy, qb, kb, yq, yk);         // 3
    cudaEventRecord(e2, 0);
    k_scores<<<dim3(4, 4, NH), 256, SC_SMEM>>>(qb, kb, Sb);                 // 4 (profiled)

    // side stream: f0 + suffix + fold
    k_f0<<<1, 512, 0, s1>>>(f0);
    cudaStreamWaitEvent(s1, e2, 0);
    dim3 gs(SP / 32, NH, 2);
    k_suffix<<<gs, 256, SUF_SMEM, s1>>>(qb, kb, qrb, krb, W_pos, b_pos, TQ, TK);
    k_fold<<<SP, 128, 0, s1>>>(TQ, TK, W_pair, RQ, RK);
    cudaEventRecord(e3, s1);

    // join -> pair2
    cudaStreamWaitEvent(0, e3, 0);
    k_pair2<<<dim3(SP, 4), 256>>>(Sb, RQ, RK, f0, W_pair, b_pair, yq, yk, out);

    cudaEventDestroy(e2);
    cudaEventDestroy(e3);
    cudaStreamDestroy(s1);
}

// round 16
// speedup vs baseline: 1.1698x; 1.0016x over previous
#include <cuda_runtime.h>
#include <cuda_fp16.h>
#include <math.h>
#include <stdint.h>

#define SP    512
#define DIN   1536
#define NH    32
#define HD    128
#define HDTOT 4096
#define KS    3072   // 2*DIN  (fp16 2-term split)

// ---------------- scratch ----------------
__device__ __half g_Xn[SP*KS];
__device__ __half g_Xg[SP*KS];
__device__ __half g_Ww[(size_t)2*HDTOT*KS];
__device__ __half g_Wy[2*HD*KS];
__device__ float g_q[SP*HDTOT];
__device__ float g_k[SP*HDTOT];
__device__ float g_yq[SP*HD];
__device__ float g_yk[SP*HD];
__device__ float g_S[(size_t)NH*SP*SP];
__device__ float g_TQ[33*SP*NH*2];
__device__ float g_TK[33*SP*NH*2];
__device__ float g_RQ[33*SP*HD*2];
__device__ float g_RK[33*SP*HD*2];
__device__ int   g_f0[SP];

// ---------------- helpers ----------------
__device__ __forceinline__ uint32_t smem_u32(const void* p) {
    uint32_t a;
    asm("{ .reg .u64 t; cvta.to.shared.u64 t, %1; cvt.u32.u64 %0, t; }" : "=r"(a) : "l"(p));
    return a;
}
__device__ __forceinline__ void cp16(uint32_t dst, const void* src) {
    asm volatile("cp.async.cg.shared.global [%0], [%1], 16;" :: "r"(dst), "l"(src));
}
#define CP_COMMIT() asm volatile("cp.async.commit_group;" ::: "memory")
#define CP_WAIT1()  asm volatile("cp.async.wait_group 1;" ::: "memory")

__device__ __forceinline__ void ldm_x4(uint32_t* r, uint32_t addr) {
    asm volatile("ldmatrix.sync.aligned.m8n8.x4.shared.b16 {%0,%1,%2,%3}, [%4];"
                 : "=r"(r[0]), "=r"(r[1]), "=r"(r[2]), "=r"(r[3]) : "r"(addr));
}
__device__ __forceinline__ void mma16816(float* c, const uint32_t* a, uint32_t b0, uint32_t b1) {
    asm volatile("mma.sync.aligned.m16n8k16.row.col.f32.f16.f16.f32 "
                 "{%0,%1,%2,%3}, {%4,%5,%6,%7}, {%8,%9}, {%0,%1,%2,%3};"
                 : "+f"(c[0]), "+f"(c[1]), "+f"(c[2]), "+f"(c[3])
                 : "r"(a[0]), "r"(a[1]), "r"(a[2]), "r"(a[3]), "r"(b0), "r"(b1));
}
__device__ __forceinline__ void split2h(float v, __half& hi, __half& lo) {
    hi = __float2half(v);
    lo = __float2half(v - __half2float(hi));
}

// BK=64: A tile 128x72 fp16 (144 B/row), B tile 256x72 fp16
#define A_TILE 18432
#define B_TILE 36864
#define STAGE_BYTES (A_TILE + B_TILE)
#define MMA_SMEM (3 * STAGE_BYTES)

__device__ __forceinline__ void mma_mainloop(
    uint32_t smb, const __half* __restrict__ Ab,
    const __half* __restrict__ Bb, int sA, int sB, int niter,
    int t, int lane, int wm, int wn, float c[4][8][4])
{
    uint32_t aoff[4], boff[4];
    {
        int lr = lane & 15, lc = lane >> 4;
        #pragma unroll
        for (int mi = 0; mi < 4; mi++) aoff[mi] = (wm * 64 + mi * 16 + lr) * 144 + lc * 16;
        #pragma unroll
        for (int nj = 0; nj < 4; nj++) boff[nj] = A_TILE + (wn * 64 + nj * 16 + lr) * 144 + lc * 16;
    }
    int lrow = t >> 3;
    int lc16 = (t & 7) * 16;
    int lcol_el = (t & 7) * 8;

    #pragma unroll
    for (int s = 0; s < 2; s++) {
        uint32_t db = smb + s * STAGE_BYTES;
        #pragma unroll
        for (int i = 0; i < 4; i++) {
            int row = lrow + i * 32;
            cp16(db + row * 144 + lc16, Ab + (size_t)row * sA + s * 64 + lcol_el);
        }
        #pragma unroll
        for (int i = 0; i < 8; i++) {
            int row = lrow + i * 32;
            cp16(db + A_TILE + row * 144 + lc16, Bb + (size_t)row * sB + s * 64 + lcol_el);
        }
        CP_COMMIT();
    }

    for (int ck = 0; ck < niter; ck++) {
        CP_WAIT1();
        __syncthreads();
        int pf = ck + 2;
        if (pf < niter) {
            uint32_t db = smb + (pf % 3) * STAGE_BYTES;
            #pragma unroll
            for (int i = 0; i < 4; i++) {
                int row = lrow + i * 32;
                cp16(db + row * 144 + lc16, Ab + (size_t)row * sA + pf * 64 + lcol_el);
            }
            #pragma unroll
            for (int i = 0; i < 8; i++) {
                int row = lrow + i * 32;
                cp16(db + A_TILE + row * 144 + lc16, Bb + (size_t)row * sB + pf * 64 + lcol_el);
            }
        }
        CP_COMMIT();
        uint32_t sa = smb + (ck % 3) * STAGE_BYTES;
        #pragma unroll
        for (int kk = 0; kk < 4; kk++) {
            uint32_t a[4][4], b[4][4];
            #pragma unroll
            for (int mi = 0; mi < 4; mi++) ldm_x4(a[mi], sa + aoff[mi] + kk * 32);
            #pragma unroll
            for (int nj = 0; nj < 4; nj++) ldm_x4(b[nj], sa + boff[nj] + kk * 32);
            #pragma unroll
            for (int mi = 0; mi < 4; mi++)
                #pragma unroll
                for (int ni = 0; ni < 8; ni++)
                    mma16816(c[mi][ni], a[mi], b[ni >> 1][ni & 1], b[ni >> 1][(ni & 1) + 2]);
        }
    }
}

// ---------------- K1: pool + rmsnorm + gelu -> fp16 [hi,lo] ----------------
__global__ void k_pool(const float* __restrict__ x, const float* __restrict__ w_rms,
                       __half* __restrict__ Xn, __half* __restrict__ Xg) {
    int sp = blockIdx.x;
    const float* xb = x + (size_t)sp * 16 * DIN;
    __shared__ float xp[DIN];
    __shared__ float red[256];
    int t = threadIdx.x;
    float ssq = 0.f;
    for (int c = t; c < DIN; c += 256) {
        float s = 0.f;
        #pragma unroll
        for (int r = 0; r < 16; r++) s += xb[r * DIN + c];
        s *= (1.f / 16.f);
        xp[c] = s;
        ssq += s * s;
    }
    red[t] = ssq;
    __syncthreads();
    for (int o = 128; o > 0; o >>= 1) {
        if (t < o) red[t] += red[t + o];
        __syncthreads();
    }
    float scale = rsqrtf(red[0] / (float)DIN + 1e-6f);
    size_t b = (size_t)sp * KS;
    for (int c = t; c < DIN; c += 256) {
        float v = xp[c] * scale * w_rms[c];
        __half hi, lo;
        split2h(v, hi, lo);
        Xn[b + c] = hi; Xn[b + DIN + c] = lo;
        float g = v * normcdff(v);
        split2h(g, hi, lo);
        Xg[b + c] = hi; Xg[b + DIN + c] = lo;
    }
}

// ---------------- K2: f0 table ----------------
__global__ void k_f0(int* __restrict__ f0) {
    int d = threadIdx.x;
    if (d < SP) {
        const float log_step = (float)(log(481.0) / 32.0);
        int cnt = 0;
        #pragma unroll
        for (int f = 0; f < 32; f++) {
            float cw = (float)f + expf((float)f * log_step);
            if (cw <= (float)d) cnt++;
        }
        f0[d] = cnt;
    }
}

// ---------------- K4: transpose weights -> fp16 [hi,hi] (merged qk + y) ----------------
__global__ void k_wsplit(const float* __restrict__ W_q, const float* __restrict__ W_k,
                         const float* __restrict__ W_yq, const float* __restrict__ W_yk,
                         __half* __restrict__ Ww, __half* __restrict__ Wy) {
    __shared__ float tile[32][33];
    int t = threadIdx.x;
    int bx = blockIdx.x, k0 = blockIdx.y * 32;
    bool isY = bx >= 256;
    int n0 = isY ? (bx - 256) * 32 : bx * 32;
    int Nsrc = isY ? HD : HDTOT;
    const float* srcA = isY ? W_yq : W_q;
    const float* srcB = isY ? W_yk : W_k;
    __half* dst = isY ? Wy : Ww;
    const float* src = (n0 < Nsrc) ? srcA : srcB;
    int nb = (n0 < Nsrc) ? n0 : (n0 - Nsrc);
    #pragma unroll
    for (int i = 0; i < 4; i++) {
        int r = (t >> 5) + i * 8, c = t & 31;
        tile[r][c] = src[(size_t)(k0 + r) * Nsrc + nb + c];
    }
    __syncthreads();
    #pragma unroll
    for (int i = 0; i < 4; i++) {
        int rn = (t >> 5) + i * 8;
        int kk = k0 + (t & 31);
        __half hi = __float2half(tile[t & 31][rn]);
        size_t row = (size_t)(n0 + rn) * KS;
        dst[row + kk] = hi;
        dst[row + DIN + kk] = hi;
    }
}

// ---------------- K5: fused projection GEMM (CTA 128x256) ----------------
__global__ void __launch_bounds__(256) k_proj(
    const __half* __restrict__ Xn, const __half* __restrict__ Xg,
    const __half* __restrict__ Ww, const __half* __restrict__ Wy,
    float* __restrict__ q, float* __restrict__ k,
    float* __restrict__ yq, float* __restrict__ yk)
{
    extern __shared__ char sm[];
    uint32_t smb = smem_u32(sm);
    int t = threadIdx.x, w = t >> 5, lane = t & 31;
    int wm = w >> 2, wn = w & 3;
    int bid = blockIdx.x;
    int mt, nt;
    if (bid < 128) { mt = bid & 3; nt = bid >> 2; }
    else { mt = bid - 128; nt = 32; }

    const __half* Ab = (bid < 128) ? (Xn + (size_t)mt * 128 * KS)
                                   : (Xg + (size_t)mt * 128 * KS);
    const __half* Bb = (nt < 32) ? (Ww + (size_t)nt * 256 * KS) : Wy;

    float c[4][8][4];
    #pragma unroll
    for (int i = 0; i < 4; i++)
        #pragma unroll
        for (int j = 0; j < 8; j++)
            #pragma unroll
            for (int e = 0; e < 4; e++) c[i][j][e] = 0.f;

    mma_mainloop(smb, Ab, Bb, KS, KS, KS / 64, t, lane, wm, wn, c);

    int r0 = lane >> 2, c0 = (lane & 3) * 2;
    int srow0 = mt * 128;
    #pragma unroll
    for (int mi = 0; mi < 4; mi++) {
        #pragma unroll
        for (int ni = 0; ni < 8; ni++) {
            #pragma unroll
            for (int half = 0; half < 2; half++) {
                int s = srow0 + wm * 64 + mi * 16 + r0 + half * 8;
                int colL = wn * 64 + ni * 8 + c0;
                float2 fv = make_float2(c[mi][ni][half * 2], c[mi][ni][half * 2 + 1]);
                if (nt < 32) {
                    int col = nt * 256 + colL;
                    bool isQ = col < HDTOT;
                    float* o = isQ ? q : k;
                    int nn = isQ ? col : col - HDTOT;
                    *(float2*)&o[(size_t)s * HDTOT + nn] = fv;
                } else {
                    float* o = (colL < HD) ? yq : yk;
                    int nn = (colL < HD) ? colL : colL - HD;
                    *(float2*)&o[(size_t)s * HD + nn] = fv;
                }
            }
        }
    }
}

// ---------------- K5s: scores GEMM, 128x128 tile, 2 CTAs/SM ----------------
#define SC_AROW 528
#define SC_BROW 272
#define SC_B_OFF (128 * SC_AROW)
#define SC_SMEM (SC_B_OFF + 128 * SC_BROW)
__global__ void __launch_bounds__(256, 2) k_scores(
    const float* __restrict__ q, const float* __restrict__ k,
    float* __restrict__ S)
{
    extern __shared__ char sm[];
    uint32_t smb = smem_u32(sm);
    int t = threadIdx.x, w = t >> 5, lane = t & 31;
    int wm = w >> 2, wn = w & 3;
    int m0 = blockIdx.x * 128, n0 = blockIdx.y * 128, z = blockIdx.z;

    for (int i = t; i < 4096; i += 256) {
        int r = i >> 5, c4 = (i & 31) * 4;
        float4 v = *(const float4*)&q[(size_t)(m0 + r) * HDTOT + z * HD + c4];
        __half h0, l0, h1, l1, h2, l2, h3, l3;
        split2h(v.x, h0, l0); split2h(v.y, h1, l1);
        split2h(v.z, h2, l2); split2h(v.w, h3, l3);
        __half* row = (__half*)(sm + r * SC_AROW);
        ((__half2*)(row + c4))[0] = __halves2half2(h0, h1);
        ((__half2*)(row + c4))[1] = __halves2half2(h2, h3);
        ((__half2*)(row + 128 + c4))[0] = __halves2half2(l0, l1);
        ((__half2*)(row + 128 + c4))[1] = __halves2half2(l2, l3);
    }
    for (int i = t; i < 4096; i += 256) {
        int r = i >> 5, c4 = (i & 31) * 4;
        float4 v = *(const float4*)&k[(size_t)(n0 + r) * HDTOT + z * HD + c4];
        __half* row = (__half*)(sm + SC_B_OFF + r * SC_BROW);
        ((__half2*)(row + c4))[0] = __halves2half2(__float2half(v.x), __float2half(v.y));
        ((__half2*)(row + c4))[1] = __halves2half2(__float2half(v.z), __float2half(v.w));
    }
    __syncthreads();

    uint32_t aoff[4], boff[2];
    {
        int lr = lane & 15, lc = lane >> 4;
        #pragma unroll
        for (int mi = 0; mi < 4; mi++) aoff[mi] = smb + (wm * 64 + mi * 16 + lr) * SC_AROW + lc * 16;
        #pragma unroll
        for (int nj = 0; nj < 2; nj++) boff[nj] = smb + SC_B_OFF + (wn * 32 + nj * 16 + lr) * SC_BROW + lc * 16;
    }
    float c[4][4][4];
    #pragma unroll
    for (int i = 0; i < 4; i++)
        #pragma unroll
        for (int j = 0; j < 4; j++)
            #pragma unroll
            for (int e = 0; e < 4; e++) c[i][j][e] = 0.f;

    #pragma unroll
    for (int kk = 0; kk < 16; kk++) {
        uint32_t a[4][4], b[2][4];
        #pragma unroll
        for (int mi = 0; mi < 4; mi++) ldm_x4(a[mi], aoff[mi] + kk * 32);
        #pragma unroll
        for (int nj = 0; nj < 2; nj++) ldm_x4(b[nj], boff[nj] + (kk & 7) * 32);
        #pragma unroll
        for (int mi = 0; mi < 4; mi++)
            #pragma unroll
            for (int ni = 0; ni < 4; ni++)
                mma16816(c[mi][ni], a[mi], b[ni >> 1][ni & 1], b[ni >> 1][(ni & 1) + 2]);
    }

    int r0 = lane >> 2, c0 = (lane & 3) * 2;
    #pragma unroll
    for (int mi = 0; mi < 4; mi++) {
        #pragma unroll
        for (int ni = 0; ni < 4; ni++) {
            #pragma unroll
            for (int half = 0; half < 2; half++) {
                int row = m0 + wm * 64 + mi * 16 + r0 + half * 8;
                int col = n0 + wn * 32 + ni * 8 + c0;
                float2 fv = make_float2(c[mi][ni][half * 2], c[mi][ni][half * 2 + 1]);
                *(float2*)&S[((size_t)(z * SP + row)) * SP + col] = fv;
            }
        }
    }
}

// ---------------- K6: suffix tables (merged TQ/TK via z) ----------------
__global__ void __launch_bounds__(256) k_suffix(const float* __restrict__ qk0,
                                                const float* __restrict__ qk1,
                                                const float* __restrict__ rb0,
                                                const float* __restrict__ rb1,
                                                const float* __restrict__ W_pos,
                                                const float* __restrict__ b_pos,
                                                float* __restrict__ T0,
                                                float* __restrict__ T1) {
    extern __shared__ float smf[];
    float* ws = smf;
    float* qs = ws + 65 * 132;
    float* Ms = qs + 32 * 132;
    int sel = blockIdx.z;
    const float* qk    = sel ? qk1 : qk0;
    const float* rbias = sel ? rb1 : rb0;
    float* T           = sel ? T1 : T0;
    int h = blockIdx.y;
    int q0 = blockIdx.x * 32;
    int t = threadIdx.x;
    for (int i = t; i < 65 * 128; i += 256) {
        int f = i >> 7, c = i & 127;
        ws[f * 132 + c] = (f < 64) ? W_pos[f * HDTOT + h * HD + c] : b_pos[h * HD + c];
    }
    for (int i = t; i < 32 * 128; i += 256) {
        int r = i >> 7, c = i & 127;
        qs[r * 132 + c] = qk[(size_t)(q0 + r) * HDTOT + h * HD + c] + rbias[h * HD + c];
    }
    __syncthreads();
    for (int i = t; i < 32 * 65; i += 256) {
        int r = i / 65, f = i % 65;
        const float4* qr = (const float4*)&qs[r * 132];
        const float4* wr = (const float4*)&ws[f * 132];
        float acc = 0.f;
        #pragma unroll
        for (int c4 = 0; c4 < 32; c4++) {
            float4 a = qr[c4], b = wr[c4];
            acc += a.x * b.x + a.y * b.y + a.z * b.z + a.w * b.w;
        }
        Ms[r * 65 + f] = acc;
    }
    __syncthreads();
    for (int i = t; i < 32 * 33; i += 256) {
        int r = i / 33, j = i % 33;
        float sa = Ms[r * 65 + 64];
        float sb = 0.f;
        for (int f = j; f < 32; f++) { sa += Ms[r * 65 + f]; sb += Ms[r * 65 + 32 + f]; }
        int q = q0 + r;
        T[((j * SP + q) * NH + h) * 2] = sa;
        T[((j * SP + q) * NH + h) * 2 + 1] = sb;
    }
}

// ---------------- K7: fold suffix tables through W_pair ----------------
__global__ void __launch_bounds__(128) k_fold(const float* __restrict__ TQ,
                                              const float* __restrict__ TK,
                                              const float* __restrict__ Wp,
                                              float* __restrict__ RQ,
                                              float* __restrict__ RK) {
    __shared__ float tq[33 * 64], tk[33 * 64];
    int q = blockIdx.x, t = threadIdx.x;
    for (int i = t; i < 33 * 64; i += 128) {
        int j = i >> 6, r = i & 63;
        tq[i] = TQ[((size_t)j * SP + q) * 64 + r];
        tk[i] = TK[((size_t)j * SP + q) * 64 + r];
    }
    float wcol[NH];
    #pragma unroll
    for (int h = 0; h < NH; h++) wcol[h] = Wp[h * HD + t];
    __syncthreads();
    for (int j = 0; j < 33; j++) {
        float aa = 0.f, ab = 0.f, ba = 0.f, bb = 0.f;
        const float* tqj = &tq[j * 64];
        const float* tkj = &tk[j * 64];
        #pragma unroll
        for (int h = 0; h < NH; h++) {
            float w = wcol[h];
            aa += tqj[2 * h] * w;  ab += tqj[2 * h + 1] * w;
            ba += tkj[2 * h] * w;  bb += tkj[2 * h + 1] * w;
        }
        size_t ob = ((size_t)j * SP + q) * 256 + t * 2;
        RQ[ob] = aa; RQ[ob + 1] = ab;
        RK[ob] = ba; RK[ob + 1] = bb;
    }
}

// ---------------- K8: final pass (FFMA2 + smem-cached RQ / j / sgn) ----------------
// smem: Sh 128*36 f (18432B) | RQs 33*256 f (33792B) | jt 128 i | sg 128 f -> 53248B
#define P2_SH   0
#define P2_RQ   (128 * 36 * 4)
#define P2_JT   (P2_RQ + 33 * 256 * 4)
#define P2_SG   (P2_JT + 128 * 4)
#define P2_SMEM (P2_SG + 128 * 4)
__global__ void __launch_bounds__(256) k_pair2(const float* __restrict__ S,
                                               const float* __restrict__ RQ,
                                               const float* __restrict__ RK,
                                               const int* __restrict__ f0tab,
                                               const float* __restrict__ Wp,
                                               const float* __restrict__ bp,
                                               const float* __restrict__ yq,
                                               const float* __restrict__ yk,
                                               float* __restrict__ out) {
    extern __shared__ __align__(16) char sm[];
    float* Sh  = (float*)(sm + P2_SH);
    float* RQs = (float*)(sm + P2_RQ);
    int*   jt  = (int*)(sm + P2_JT);
    float* sg  = (float*)(sm + P2_SG);
    int t = threadIdx.x;
    int q = blockIdx.x, k0 = blockIdx.y * 128;

    for (int i = t; i < 4096; i += 256) {
        int h = i >> 7, kk = i & 127;
        Sh[kk * 36 + h] = S[(((size_t)h * SP + q) << 9) + k0 + kk];
    }
    // cache all 33 RQ rows for this q (coalesced)
    for (int i = t; i < 33 * 256; i += 256) {
        int j = i >> 8, c = i & 255;
        RQs[i] = RQ[((size_t)j * SP + q) * 256 + c];
    }
    if (t < 128) {
        int k = k0 + t;
        int delta = k - q;
        int dd = delta >= 0 ? delta : -delta;
        jt[t] = f0tab[dd];
        sg[t] = delta > 0 ? 0.5f : (delta < 0 ? -0.5f : 0.f);
    }
    int d = t & 127, g = t >> 7;
    uint64_t w2[16];
    #pragma unroll
    for (int h2 = 0; h2 < 16; h2++) {
        float w0 = Wp[(2 * h2) * HD + d], w1 = Wp[(2 * h2 + 1) * HD + d];
        asm("mov.b64 %0, {%1,%2};" : "=l"(w2[h2]) : "f"(w0), "f"(w1));
    }
    float base0 = bp[d] + yq[q * HD + d];
    __syncthreads();

    #pragma unroll 2
    for (int kk = g * 64; kk < g * 64 + 64; kk++) {
        int k = k0 + kk;
        int j = jt[kk];
        float sgn = sg[kk];
        float2 rq = *(const float2*)&RQs[j * 256 + d * 2];
        float2 rk = *(const float2*)&RK[((size_t)j * SP + k) * 256 + d * 2];
        float base = base0 + yk[k * HD + d]
                   + 0.5f * (rq.x + rk.x) + sgn * (rq.y - rk.y);
        const ulonglong2* sr2 = (const ulonglong2*)&Sh[kk * 36];
        uint64_t acc2 = 0;
        #pragma unroll
        for (int h8 = 0; h8 < 8; h8++) {
            ulonglong2 v = sr2[h8];
            asm("fma.rn.f32x2 %0, %1, %2, %0;" : "+l"(acc2) : "l"(v.x), "l"(w2[h8 * 2]));
            asm("fma.rn.f32x2 %0, %1, %2, %0;" : "+l"(acc2) : "l"(v.y), "l"(w2[h8 * 2 + 1]));
        }
        float lo, hi;
        asm("mov.b64 {%0,%1}, %2;" : "=f"(lo), "=f"(hi) : "l"(acc2));
        out[((size_t)(q * SP + k)) * HD + d] = base + lo + hi;
    }
}

// ---------------- launcher ----------------
#define SUF_SMEM ((65 * 132 + 32 * 132 + 32 * 65) * 4)

extern "C" void kernel_launch(void* const* d_in, const int* in_sizes, int n_in,
                              void* d_out, int out_size) {
    const float* x      = (const float*)d_in[0];
    const float* w_rms  = (const float*)d_in[1];
    const float* W_q    = (const float*)d_in[2];
    const float* W_k    = (const float*)d_in[3];
    const float* W_pos  = (const float*)d_in[4];
    const float* b_pos  = (const float*)d_in[5];
    const float* qrb    = (const float*)d_in[6];
    const float* krb    = (const float*)d_in[7];
    const float* W_yq   = (const float*)d_in[8];
    const float* W_yk   = (const float*)d_in[9];
    const float* W_pair = (const float*)d_in[10];
    const float* b_pair = (const float*)d_in[11];
    float* out = (float*)d_out;

    float *qb, *kb, *yq, *yk, *TQ, *TK, *RQ, *RK, *Sb;
    __half *Xn, *Xg, *Ww, *Wy;
    int* f0;
    cudaGetSymbolAddress((void**)&qb, g_q);
    cudaGetSymbolAddress((void**)&kb, g_k);
    cudaGetSymbolAddress((void**)&yq, g_yq);
    cudaGetSymbolAddress((void**)&yk, g_yk);
    cudaGetSymbolAddress((void**)&TQ, g_TQ);
    cudaGetSymbolAddress((void**)&TK, g_TK);
    cudaGetSymbolAddress((void**)&RQ, g_RQ);
    cudaGetSymbolAddress((void**)&RK, g_RK);
    cudaGetSymbolAddress((void**)&Sb, g_S);
    cudaGetSymbolAddress((void**)&Xn, g_Xn);
    cudaGetSymbolAddress((void**)&Xg, g_Xg);
    cudaGetSymbolAddress((void**)&Ww, g_Ww);
    cudaGetSymbolAddress((void**)&Wy, g_Wy);
    cudaGetSymbolAddress((void**)&f0, g_f0);

    cudaFuncSetAttribute(k_proj, cudaFuncAttributeMaxDynamicSharedMemorySize, MMA_SMEM);
    cudaFuncSetAttribute(k_scores, cudaFuncAttributeMaxDynamicSharedMemorySize, SC_SMEM);
    cudaFuncSetAttribute(k_suffix, cudaFuncAttributeMaxDynamicSharedMemorySize, SUF_SMEM);
    cudaFuncSetAttribute(k_pair2, cudaFuncAttributeMaxDynamicSharedMemorySize, P2_SMEM);

    cudaStream_t s1;
    cudaStreamCreateWithFlags(&s1, cudaStreamNonBlocking);
    cudaEvent_t e2, e3;
    cudaEventCreateWithFlags(&e2, cudaEventDisableTiming);
    cudaEventCreateWithFlags(&e3, cudaEventDisableTiming);

    // default stream critical path
    k_wsplit<<<dim3(264, DIN / 32), 256>>>(W_q, W_k, W_yq, W_yk, Ww, Wy);   // 1
    k_pool<<<SP, 256>>>(x, w_rms, Xn, Xg);                                  // 2
    k_proj<<<132, 256, MMA_SMEM>>>(Xn, Xg, Ww, Wy, qb, kb, yq, yk);         // 3
    cudaEventRecord(e2, 0);
    k_scores<<<dim3(4, 4, NH), 256, SC_SMEM>>>(qb, kb, Sb);                 // 4 (profiled)

    // side stream: f0 + suffix + fold
    k_f0<<<1, 512, 0, s1>>>(f0);
    cudaStreamWaitEvent(s1, e2, 0);
    dim3 gs(SP / 32, NH, 2);
    k_suffix<<<gs, 256, SUF_SMEM, s1>>>(qb, kb, qrb, krb, W_pos, b_pos, TQ, TK);
    k_fold<<<SP, 128, 0, s1>>>(TQ, TK, W_pair, RQ, RK);
    cudaEventRecord(e3, s1);

    // join -> pair2
    cudaStreamWaitEvent(0, e3, 0);
    k_pair2<<<dim3(SP, 4), 256, P2_SMEM>>>(Sb, RQ, RK, f0, W_pair, b_pair, yq, yk, out);

    cudaEventDestroy(e2);
    cudaEventDestroy(e3);
    cudaStreamDestroy(s1);
}

// round 17
// speedup vs baseline: 1.3296x; 1.1366x over previous
#include <cuda_runtime.h>
#include <cuda_fp16.h>
#include <math.h>
#include <stdint.h>

#define SP    512
#define DIN   1536
#define NH    32
#define HD    128
#define HDTOT 4096
#define KS    1536   // single fp16 hi-term for projections

// ---------------- scratch ----------------
__device__ __half g_Xn[SP*KS];
__device__ __half g_Xg[SP*KS];
__device__ __half g_Ww[(size_t)2*HDTOT*KS];
__device__ __half g_Wy[2*HD*KS];
__device__ float g_q[SP*HDTOT];
__device__ float g_k[SP*HDTOT];
__device__ float g_yq[SP*HD];
__device__ float g_yk[SP*HD];
__device__ float g_S[(size_t)NH*SP*SP];
__device__ float g_TQ[33*SP*NH*2];
__device__ float g_TK[33*SP*NH*2];
__device__ float g_RQ[33*SP*HD*2];
__device__ float g_RK[33*SP*HD*2];
__device__ int   g_f0[SP];

// ---------------- helpers ----------------
__device__ __forceinline__ uint32_t smem_u32(const void* p) {
    uint32_t a;
    asm("{ .reg .u64 t; cvta.to.shared.u64 t, %1; cvt.u32.u64 %0, t; }" : "=r"(a) : "l"(p));
    return a;
}
__device__ __forceinline__ void cp16(uint32_t dst, const void* src) {
    asm volatile("cp.async.cg.shared.global [%0], [%1], 16;" :: "r"(dst), "l"(src));
}
#define CP_COMMIT() asm volatile("cp.async.commit_group;" ::: "memory")
#define CP_WAIT1()  asm volatile("cp.async.wait_group 1;" ::: "memory")

__device__ __forceinline__ void ldm_x4(uint32_t* r, uint32_t addr) {
    asm volatile("ldmatrix.sync.aligned.m8n8.x4.shared.b16 {%0,%1,%2,%3}, [%4];"
                 : "=r"(r[0]), "=r"(r[1]), "=r"(r[2]), "=r"(r[3]) : "r"(addr));
}
__device__ __forceinline__ void mma16816(float* c, const uint32_t* a, uint32_t b0, uint32_t b1) {
    asm volatile("mma.sync.aligned.m16n8k16.row.col.f32.f16.f16.f32 "
                 "{%0,%1,%2,%3}, {%4,%5,%6,%7}, {%8,%9}, {%0,%1,%2,%3};"
                 : "+f"(c[0]), "+f"(c[1]), "+f"(c[2]), "+f"(c[3])
                 : "r"(a[0]), "r"(a[1]), "r"(a[2]), "r"(a[3]), "r"(b0), "r"(b1));
}
__device__ __forceinline__ void split2h(float v, __half& hi, __half& lo) {
    hi = __float2half(v);
    lo = __float2half(v - __half2float(hi));
}

// BK=64: A tile 128x72 fp16 (144 B/row), B tile 256x72 fp16
#define A_TILE 18432
#define B_TILE 36864
#define STAGE_BYTES (A_TILE + B_TILE)
#define MMA_SMEM (3 * STAGE_BYTES)

__device__ __forceinline__ void mma_mainloop(
    uint32_t smb, const __half* __restrict__ Ab,
    const __half* __restrict__ Bb, int sA, int sB, int niter,
    int t, int lane, int wm, int wn, float c[4][8][4])
{
    uint32_t aoff[4], boff[4];
    {
        int lr = lane & 15, lc = lane >> 4;
        #pragma unroll
        for (int mi = 0; mi < 4; mi++) aoff[mi] = (wm * 64 + mi * 16 + lr) * 144 + lc * 16;
        #pragma unroll
        for (int nj = 0; nj < 4; nj++) boff[nj] = A_TILE + (wn * 64 + nj * 16 + lr) * 144 + lc * 16;
    }
    int lrow = t >> 3;
    int lc16 = (t & 7) * 16;
    int lcol_el = (t & 7) * 8;

    #pragma unroll
    for (int s = 0; s < 2; s++) {
        uint32_t db = smb + s * STAGE_BYTES;
        #pragma unroll
        for (int i = 0; i < 4; i++) {
            int row = lrow + i * 32;
            cp16(db + row * 144 + lc16, Ab + (size_t)row * sA + s * 64 + lcol_el);
        }
        #pragma unroll
        for (int i = 0; i < 8; i++) {
            int row = lrow + i * 32;
            cp16(db + A_TILE + row * 144 + lc16, Bb + (size_t)row * sB + s * 64 + lcol_el);
        }
        CP_COMMIT();
    }

    for (int ck = 0; ck < niter; ck++) {
        CP_WAIT1();
        __syncthreads();
        int pf = ck + 2;
        if (pf < niter) {
            uint32_t db = smb + (pf % 3) * STAGE_BYTES;
            #pragma unroll
            for (int i = 0; i < 4; i++) {
                int row = lrow + i * 32;
                cp16(db + row * 144 + lc16, Ab + (size_t)row * sA + pf * 64 + lcol_el);
            }
            #pragma unroll
            for (int i = 0; i < 8; i++) {
                int row = lrow + i * 32;
                cp16(db + A_TILE + row * 144 + lc16, Bb + (size_t)row * sB + pf * 64 + lcol_el);
            }
        }
        CP_COMMIT();
        uint32_t sa = smb + (ck % 3) * STAGE_BYTES;
        #pragma unroll
        for (int kk = 0; kk < 4; kk++) {
            uint32_t a[4][4], b[4][4];
            #pragma unroll
            for (int mi = 0; mi < 4; mi++) ldm_x4(a[mi], sa + aoff[mi] + kk * 32);
            #pragma unroll
            for (int nj = 0; nj < 4; nj++) ldm_x4(b[nj], sa + boff[nj] + kk * 32);
            #pragma unroll
            for (int mi = 0; mi < 4; mi++)
                #pragma unroll
                for (int ni = 0; ni < 8; ni++)
                    mma16816(c[mi][ni], a[mi], b[ni >> 1][ni & 1], b[ni >> 1][(ni & 1) + 2]);
        }
    }
}

// ---------------- K1: pool + rmsnorm + gelu -> fp16 hi ----------------
__global__ void k_pool(const float* __restrict__ x, const float* __restrict__ w_rms,
                       __half* __restrict__ Xn, __half* __restrict__ Xg) {
    int sp = blockIdx.x;
    const float* xb = x + (size_t)sp * 16 * DIN;
    __shared__ float xp[DIN];
    __shared__ float red[256];
    int t = threadIdx.x;
    float ssq = 0.f;
    for (int c = t; c < DIN; c += 256) {
        float s = 0.f;
        #pragma unroll
        for (int r = 0; r < 16; r++) s += xb[r * DIN + c];
        s *= (1.f / 16.f);
        xp[c] = s;
        ssq += s * s;
    }
    red[t] = ssq;
    __syncthreads();
    for (int o = 128; o > 0; o >>= 1) {
        if (t < o) red[t] += red[t + o];
        __syncthreads();
    }
    float scale = rsqrtf(red[0] / (float)DIN + 1e-6f);
    size_t b = (size_t)sp * KS;
    for (int c = t; c < DIN; c += 256) {
        float v = xp[c] * scale * w_rms[c];
        Xn[b + c] = __float2half(v);
        Xg[b + c] = __float2half(v * normcdff(v));
    }
}

// ---------------- K2: f0 table ----------------
__global__ void k_f0(int* __restrict__ f0) {
    int d = threadIdx.x;
    if (d < SP) {
        const float log_step = (float)(log(481.0) / 32.0);
        int cnt = 0;
        #pragma unroll
        for (int f = 0; f < 32; f++) {
            float cw = (float)f + expf((float)f * log_step);
            if (cw <= (float)d) cnt++;
        }
        f0[d] = cnt;
    }
}

// ---------------- K4: transpose weights -> fp16 hi (merged qk + y) ----------------
__global__ void k_wsplit(const float* __restrict__ W_q, const float* __restrict__ W_k,
                         const float* __restrict__ W_yq, const float* __restrict__ W_yk,
                         __half* __restrict__ Ww, __half* __restrict__ Wy) {
    __shared__ float tile[32][33];
    int t = threadIdx.x;
    int bx = blockIdx.x, k0 = blockIdx.y * 32;
    bool isY = bx >= 256;
    int n0 = isY ? (bx - 256) * 32 : bx * 32;
    int Nsrc = isY ? HD : HDTOT;
    const float* srcA = isY ? W_yq : W_q;
    const float* srcB = isY ? W_yk : W_k;
    __half* dst = isY ? Wy : Ww;
    const float* src = (n0 < Nsrc) ? srcA : srcB;
    int nb = (n0 < Nsrc) ? n0 : (n0 - Nsrc);
    #pragma unroll
    for (int i = 0; i < 4; i++) {
        int r = (t >> 5) + i * 8, c = t & 31;
        tile[r][c] = src[(size_t)(k0 + r) * Nsrc + nb + c];
    }
    __syncthreads();
    #pragma unroll
    for (int i = 0; i < 4; i++) {
        int rn = (t >> 5) + i * 8;
        int kk = k0 + (t & 31);
        dst[(size_t)(n0 + rn) * KS + kk] = __float2half(tile[t & 31][rn]);
    }
}

// ---------------- K5: fused projection GEMM (CTA 128x256, K=1536) ----------------
__global__ void __launch_bounds__(256) k_proj(
    const __half* __restrict__ Xn, const __half* __restrict__ Xg,
    const __half* __restrict__ Ww, const __half* __restrict__ Wy,
    float* __restrict__ q, float* __restrict__ k,
    float* __restrict__ yq, float* __restrict__ yk)
{
    extern __shared__ char sm[];
    uint32_t smb = smem_u32(sm);
    int t = threadIdx.x, w = t >> 5, lane = t & 31;
    int wm = w >> 2, wn = w & 3;
    int bid = blockIdx.x;
    int mt, nt;
    if (bid < 128) { mt = bid & 3; nt = bid >> 2; }
    else { mt = bid - 128; nt = 32; }

    const __half* Ab = (bid < 128) ? (Xn + (size_t)mt * 128 * KS)
                                   : (Xg + (size_t)mt * 128 * KS);
    const __half* Bb = (nt < 32) ? (Ww + (size_t)nt * 256 * KS) : Wy;

    float c[4][8][4];
    #pragma unroll
    for (int i = 0; i < 4; i++)
        #pragma unroll
        for (int j = 0; j < 8; j++)
            #pragma unroll
            for (int e = 0; e < 4; e++) c[i][j][e] = 0.f;

    mma_mainloop(smb, Ab, Bb, KS, KS, KS / 64, t, lane, wm, wn, c);

    int r0 = lane >> 2, c0 = (lane & 3) * 2;
    int srow0 = mt * 128;
    #pragma unroll
    for (int mi = 0; mi < 4; mi++) {
        #pragma unroll
        for (int ni = 0; ni < 8; ni++) {
            #pragma unroll
            for (int half = 0; half < 2; half++) {
                int s = srow0 + wm * 64 + mi * 16 + r0 + half * 8;
                int colL = wn * 64 + ni * 8 + c0;
                float2 fv = make_float2(c[mi][ni][half * 2], c[mi][ni][half * 2 + 1]);
                if (nt < 32) {
                    int col = nt * 256 + colL;
                    bool isQ = col < HDTOT;
                    float* o = isQ ? q : k;
                    int nn = isQ ? col : col - HDTOT;
                    *(float2*)&o[(size_t)s * HDTOT + nn] = fv;
                } else {
                    float* o = (colL < HD) ? yq : yk;
                    int nn = (colL < HD) ? colL : colL - HD;
                    *(float2*)&o[(size_t)s * HD + nn] = fv;
                }
            }
        }
    }
}

// ---------------- K5s: scores GEMM, 128x128 tile, 2 CTAs/SM ----------------
#define SC_AROW 528
#define SC_BROW 272
#define SC_B_OFF (128 * SC_AROW)
#define SC_SMEM (SC_B_OFF + 128 * SC_BROW)
__global__ void __launch_bounds__(256, 2) k_scores(
    const float* __restrict__ q, const float* __restrict__ k,
    float* __restrict__ S)
{
    extern __shared__ char sm[];
    uint32_t smb = smem_u32(sm);
    int t = threadIdx.x, w = t >> 5, lane = t & 31;
    int wm = w >> 2, wn = w & 3;
    int m0 = blockIdx.x * 128, n0 = blockIdx.y * 128, z = blockIdx.z;

    for (int i = t; i < 4096; i += 256) {
        int r = i >> 5, c4 = (i & 31) * 4;
        float4 v = *(const float4*)&q[(size_t)(m0 + r) * HDTOT + z * HD + c4];
        __half h0, l0, h1, l1, h2, l2, h3, l3;
        split2h(v.x, h0, l0); split2h(v.y, h1, l1);
        split2h(v.z, h2, l2); split2h(v.w, h3, l3);
        __half* row = (__half*)(sm + r * SC_AROW);
        ((__half2*)(row + c4))[0] = __halves2half2(h0, h1);
        ((__half2*)(row + c4))[1] = __halves2half2(h2, h3);
        ((__half2*)(row + 128 + c4))[0] = __halves2half2(l0, l1);
        ((__half2*)(row + 128 + c4))[1] = __halves2half2(l2, l3);
    }
    for (int i = t; i < 4096; i += 256) {
        int r = i >> 5, c4 = (i & 31) * 4;
        float4 v = *(const float4*)&k[(size_t)(n0 + r) * HDTOT + z * HD + c4];
        __half* row = (__half*)(sm + SC_B_OFF + r * SC_BROW);
        ((__half2*)(row + c4))[0] = __halves2half2(__float2half(v.x), __float2half(v.y));
        ((__half2*)(row + c4))[1] = __halves2half2(__float2half(v.z), __float2half(v.w));
    }
    __syncthreads();

    uint32_t aoff[4], boff[2];
    {
        int lr = lane & 15, lc = lane >> 4;
        #pragma unroll
        for (int mi = 0; mi < 4; mi++) aoff[mi] = smb + (wm * 64 + mi * 16 + lr) * SC_AROW + lc * 16;
        #pragma unroll
        for (int nj = 0; nj < 2; nj++) boff[nj] = smb + SC_B_OFF + (wn * 32 + nj * 16 + lr) * SC_BROW + lc * 16;
    }
    float c[4][4][4];
    #pragma unroll
    for (int i = 0; i < 4; i++)
        #pragma unroll
        for (int j = 0; j < 4; j++)
            #pragma unroll
            for (int e = 0; e < 4; e++) c[i][j][e] = 0.f;

    #pragma unroll
    for (int kk = 0; kk < 16; kk++) {
        uint32_t a[4][4], b[2][4];
        #pragma unroll
        for (int mi = 0; mi < 4; mi++) ldm_x4(a[mi], aoff[mi] + kk * 32);
        #pragma unroll
        for (int nj = 0; nj < 2; nj++) ldm_x4(b[nj], boff[nj] + (kk & 7) * 32);
        #pragma unroll
        for (int mi = 0; mi < 4; mi++)
            #pragma unroll
            for (int ni = 0; ni < 4; ni++)
                mma16816(c[mi][ni], a[mi], b[ni >> 1][ni & 1], b[ni >> 1][(ni & 1) + 2]);
    }

    int r0 = lane >> 2, c0 = (lane & 3) * 2;
    #pragma unroll
    for (int mi = 0; mi < 4; mi++) {
        #pragma unroll
        for (int ni = 0; ni < 4; ni++) {
            #pragma unroll
            for (int half = 0; half < 2; half++) {
                int row = m0 + wm * 64 + mi * 16 + r0 + half * 8;
                int col = n0 + wn * 32 + ni * 8 + c0;
                float2 fv = make_float2(c[mi][ni][half * 2], c[mi][ni][half * 2 + 1]);
                *(float2*)&S[((size_t)(z * SP + row)) * SP + col] = fv;
            }
        }
    }
}

// ---------------- K6: suffix tables (merged TQ/TK via z) ----------------
__global__ void __launch_bounds__(256) k_suffix(const float* __restrict__ qk0,
                                                const float* __restrict__ qk1,
                                                const float* __restrict__ rb0,
                                                const float* __restrict__ rb1,
                                                const float* __restrict__ W_pos,
                                                const float* __restrict__ b_pos,
                                                float* __restrict__ T0,
                                                float* __restrict__ T1) {
    extern __shared__ float smf[];
    float* ws = smf;
    float* qs = ws + 65 * 132;
    float* Ms = qs + 32 * 132;
    int sel = blockIdx.z;
    const float* qk    = sel ? qk1 : qk0;
    const float* rbias = sel ? rb1 : rb0;
    float* T           = sel ? T1 : T0;
    int h = blockIdx.y;
    int q0 = blockIdx.x * 32;
    int t = threadIdx.x;
    for (int i = t; i < 65 * 128; i += 256) {
        int f = i >> 7, c = i & 127;
        ws[f * 132 + c] = (f < 64) ? W_pos[f * HDTOT + h * HD + c] : b_pos[h * HD + c];
    }
    for (int i = t; i < 32 * 128; i += 256) {
        int r = i >> 7, c = i & 127;
        qs[r * 132 + c] = qk[(size_t)(q0 + r) * HDTOT + h * HD + c] + rbias[h * HD + c];
    }
    __syncthreads();
    for (int i = t; i < 32 * 65; i += 256) {
        int r = i / 65, f = i % 65;
        const float4* qr = (const float4*)&qs[r * 132];
        const float4* wr = (const float4*)&ws[f * 132];
        float acc = 0.f;
        #pragma unroll
        for (int c4 = 0; c4 < 32; c4++) {
            float4 a = qr[c4], b = wr[c4];
            acc += a.x * b.x + a.y * b.y + a.z * b.z + a.w * b.w;
        }
        Ms[r * 65 + f] = acc;
    }
    __syncthreads();
    for (int i = t; i < 32 * 33; i += 256) {
        int r = i / 33, j = i % 33;
        float sa = Ms[r * 65 + 64];
        float sb = 0.f;
        for (int f = j; f < 32; f++) { sa += Ms[r * 65 + f]; sb += Ms[r * 65 + 32 + f]; }
        int q = q0 + r;
        T[((j * SP + q) * NH + h) * 2] = sa;
        T[((j * SP + q) * NH + h) * 2 + 1] = sb;
    }
}

// ---------------- K7: fold suffix tables through W_pair ----------------
__global__ void __launch_bounds__(128) k_fold(const float* __restrict__ TQ,
                                              const float* __restrict__ TK,
                                              const float* __restrict__ Wp,
                                              float* __restrict__ RQ,
                                              float* __restrict__ RK) {
    __shared__ float tq[33 * 64], tk[33 * 64];
    int q = blockIdx.x, t = threadIdx.x;
    for (int i = t; i < 33 * 64; i += 128) {
        int j = i >> 6, r = i & 63;
        tq[i] = TQ[((size_t)j * SP + q) * 64 + r];
        tk[i] = TK[((size_t)j * SP + q) * 64 + r];
    }
    float wcol[NH];
    #pragma unroll
    for (int h = 0; h < NH; h++) wcol[h] = Wp[h * HD + t];
    __syncthreads();
    for (int j = 0; j < 33; j++) {
        float aa = 0.f, ab = 0.f, ba = 0.f, bb = 0.f;
        const float* tqj = &tq[j * 64];
        const float* tkj = &tk[j * 64];
        #pragma unroll
        for (int h = 0; h < NH; h++) {
            float w = wcol[h];
            aa += tqj[2 * h] * w;  ab += tqj[2 * h + 1] * w;
            ba += tkj[2 * h] * w;  bb += tkj[2 * h + 1] * w;
        }
        size_t ob = ((size_t)j * SP + q) * 256 + t * 2;
        RQ[ob] = aa; RQ[ob + 1] = ab;
        RK[ob] = ba; RK[ob + 1] = bb;
    }
}

// ---------------- K8: final pass (FFMA2 + smem-cached RQ / j / sgn) ----------------
#define P2_SH   0
#define P2_RQ   (128 * 36 * 4)
#define P2_JT   (P2_RQ + 33 * 256 * 4)
#define P2_SG   (P2_JT + 128 * 4)
#define P2_SMEM (P2_SG + 128 * 4)
__global__ void __launch_bounds__(256) k_pair2(const float* __restrict__ S,
                                               const float* __restrict__ RQ,
                                               const float* __restrict__ RK,
                                               const int* __restrict__ f0tab,
                                               const float* __restrict__ Wp,
                                               const float* __restrict__ bp,
                                               const float* __restrict__ yq,
                                               const float* __restrict__ yk,
                                               float* __restrict__ out) {
    extern __shared__ __align__(16) char sm[];
    float* Sh  = (float*)(sm + P2_SH);
    float* RQs = (float*)(sm + P2_RQ);
    int*   jt  = (int*)(sm + P2_JT);
    float* sg  = (float*)(sm + P2_SG);
    int t = threadIdx.x;
    int q = blockIdx.x, k0 = blockIdx.y * 128;

    for (int i = t; i < 4096; i += 256) {
        int h = i >> 7, kk = i & 127;
        Sh[kk * 36 + h] = S[(((size_t)h * SP + q) << 9) + k0 + kk];
    }
    for (int i = t; i < 33 * 256; i += 256) {
        int j = i >> 8, c = i & 255;
        RQs[i] = RQ[((size_t)j * SP + q) * 256 + c];
    }
    if (t < 128) {
        int k = k0 + t;
        int delta = k - q;
        int dd = delta >= 0 ? delta : -delta;
        jt[t] = f0tab[dd];
        sg[t] = delta > 0 ? 0.5f : (delta < 0 ? -0.5f : 0.f);
    }
    int d = t & 127, g = t >> 7;
    uint64_t w2[16];
    #pragma unroll
    for (int h2 = 0; h2 < 16; h2++) {
        float w0 = Wp[(2 * h2) * HD + d], w1 = Wp[(2 * h2 + 1) * HD + d];
        asm("mov.b64 %0, {%1,%2};" : "=l"(w2[h2]) : "f"(w0), "f"(w1));
    }
    float base0 = bp[d] + yq[q * HD + d];
    __syncthreads();

    #pragma unroll 2
    for (int kk = g * 64; kk < g * 64 + 64; kk++) {
        int k = k0 + kk;
        int j = jt[kk];
        float sgn = sg[kk];
        float2 rq = *(const float2*)&RQs[j * 256 + d * 2];
        float2 rk = *(const float2*)&RK[((size_t)j * SP + k) * 256 + d * 2];
        float base = base0 + yk[k * HD + d]
                   + 0.5f * (rq.x + rk.x) + sgn * (rq.y - rk.y);
        const ulonglong2* sr2 = (const ulonglong2*)&Sh[kk * 36];
        uint64_t acc2 = 0;
        #pragma unroll
        for (int h8 = 0; h8 < 8; h8++) {
            ulonglong2 v = sr2[h8];
            asm("fma.rn.f32x2 %0, %1, %2, %0;" : "+l"(acc2) : "l"(v.x), "l"(w2[h8 * 2]));
            asm("fma.rn.f32x2 %0, %1, %2, %0;" : "+l"(acc2) : "l"(v.y), "l"(w2[h8 * 2 + 1]));
        }
        float lo, hi;
        asm("mov.b64 {%0,%1}, %2;" : "=f"(lo), "=f"(hi) : "l"(acc2));
        out[((size_t)(q * SP + k)) * HD + d] = base + lo + hi;
    }
}

// ---------------- launcher ----------------
#define SUF_SMEM ((65 * 132 + 32 * 132 + 32 * 65) * 4)

extern "C" void kernel_launch(void* const* d_in, const int* in_sizes, int n_in,
                              void* d_out, int out_size) {
    const float* x      = (const float*)d_in[0];
    const float* w_rms  = (const float*)d_in[1];
    const float* W_q    = (const float*)d_in[2];
    const float* W_k    = (const float*)d_in[3];
    const float* W_pos  = (const float*)d_in[4];
    const float* b_pos  = (const float*)d_in[5];
    const float* qrb    = (const float*)d_in[6];
    const float* krb    = (const float*)d_in[7];
    const float* W_yq   = (const float*)d_in[8];
    const float* W_yk   = (const float*)d_in[9];
    const float* W_pair = (const float*)d_in[10];
    const float* b_pair = (const float*)d_in[11];
    float* out = (float*)d_out;

    float *qb, *kb, *yq, *yk, *TQ, *TK, *RQ, *RK, *Sb;
    __half *Xn, *Xg, *Ww, *Wy;
    int* f0;
    cudaGetSymbolAddress((void**)&qb, g_q);
    cudaGetSymbolAddress((void**)&kb, g_k);
    cudaGetSymbolAddress((void**)&yq, g_yq);
    cudaGetSymbolAddress((void**)&yk, g_yk);
    cudaGetSymbolAddress((void**)&TQ, g_TQ);
    cudaGetSymbolAddress((void**)&TK, g_TK);
    cudaGetSymbolAddress((void**)&RQ, g_RQ);
    cudaGetSymbolAddress((void**)&RK, g_RK);
    cudaGetSymbolAddress((void**)&Sb, g_S);
    cudaGetSymbolAddress((void**)&Xn, g_Xn);
    cudaGetSymbolAddress((void**)&Xg, g_Xg);
    cudaGetSymbolAddress((void**)&Ww, g_Ww);
    cudaGetSymbolAddress((void**)&Wy, g_Wy);
    cudaGetSymbolAddress((void**)&f0, g_f0);

    cudaFuncSetAttribute(k_proj, cudaFuncAttributeMaxDynamicSharedMemorySize, MMA_SMEM);
    cudaFuncSetAttribute(k_scores, cudaFuncAttributeMaxDynamicSharedMemorySize, SC_SMEM);
    cudaFuncSetAttribute(k_suffix, cudaFuncAttributeMaxDynamicSharedMemorySize, SUF_SMEM);
    cudaFuncSetAttribute(k_pair2, cudaFuncAttributeMaxDynamicSharedMemorySize, P2_SMEM);

    cudaStream_t s1;
    cudaStreamCreateWithFlags(&s1, cudaStreamNonBlocking);
    cudaEvent_t e2, e3;
    cudaEventCreateWithFlags(&e2, cudaEventDisableTiming);
    cudaEventCreateWithFlags(&e3, cudaEventDisableTiming);

    // default stream critical path
    k_wsplit<<<dim3(264, DIN / 32), 256>>>(W_q, W_k, W_yq, W_yk, Ww, Wy);   // 1
    k_pool<<<SP, 256>>>(x, w_rms, Xn, Xg);                                  // 2
    k_proj<<<132, 256, MMA_SMEM>>>(Xn, Xg, Ww, Wy, qb, kb, yq, yk);         // 3
    cudaEventRecord(e2, 0);
    k_scores<<<dim3(4, 4, NH), 256, SC_SMEM>>>(qb, kb, Sb);                 // 4 (profiled)

    // side stream: f0 + suffix + fold
    k_f0<<<1, 512, 0, s1>>>(f0);
    cudaStreamWaitEvent(s1, e2, 0);
    dim3 gs(SP / 32, NH, 2);
    k_suffix<<<gs, 256, SUF_SMEM, s1>>>(qb, kb, qrb, krb, W_pos, b_pos, TQ, TK);
    k_fold<<<SP, 128, 0, s1>>>(TQ, TK, W_pair, RQ, RK);
    cudaEventRecord(e3, s1);

    // join -> pair2
    cudaStreamWaitEvent(0, e3, 0);
    k_pair2<<<dim3(SP, 4), 256, P2_SMEM>>>(Sb, RQ, RK, f0, W_pair, b_pair, yq, yk, out);

    cudaEventDestroy(e2);
    cudaEventDestroy(e3);
    cudaStreamDestroy(s1);
}